// round 12
// baseline (speedup 1.0000x reference)
#include <cuda_runtime.h>
#include <cuda_fp16.h>
#include <cstdint>
#include <cstddef>

#define BATCH 64
#define PIX   196
#define ENCD  2048
#define ATTD  512
#define EMBD  512
#define DECD  512
#define VOCAB 20000
#define MAXLN 22
#define TSTEP 21
#define XDIM  3072
#define MROWS 1408   // 11*128 >= 21*64=1344

// ---------------- fp32 scratch ----------------
__device__ float g_h[BATCH * DECD];
__device__ float g_c[BATCH * DECD];
__device__ float g_scores[BATCH * PIX];
__device__ __align__(16) float g_part[16 * BATCH * 2560];

// ---------------- fp16 activations ----------------
__device__ __align__(16) __half g_att1h[BATCH * PIX * ATTD];
__device__ __align__(16) __half g_ench[BATCH * PIX * ENCD];
__device__ __align__(16) __half g_meanh[BATCH * ENCD];
__device__ __align__(16) __half g_hh[BATCH * DECD];
__device__ __align__(16) __half g_xh[BATCH * XDIM];
__device__ __align__(16) __half g_hallh[MROWS * DECD];

// ---------------- fp16 weights ----------------
__device__ __align__(16) __half g_w_att[ATTD * ATTD];
__device__ __align__(16) __half g_w_fb[DECD * ENCD];
__device__ __align__(16) __half g_w_ih[(EMBD + ENCD) * 2048];
__device__ __align__(16) __half g_w_hh[DECD * 2048];
__device__ __align__(16) __half g_w_enc[ENCD * ATTD];
__device__ __align__(16) __half g_w_h0[ENCD * DECD];
__device__ __align__(16) __half g_w_c0[ENCD * DECD];
__device__ __align__(16) __half g_w_fc[DECD * VOCAB];

// ---------------------------------------------------------------------------
__device__ __forceinline__ void mma_f16(float* d, const uint32_t* a, const uint32_t* b) {
    asm volatile(
        "mma.sync.aligned.m16n8k16.row.col.f32.f16.f16.f32 "
        "{%0,%1,%2,%3}, {%4,%5,%6,%7}, {%8,%9}, {%0,%1,%2,%3};\n"
        : "+f"(d[0]), "+f"(d[1]), "+f"(d[2]), "+f"(d[3])
        : "r"(a[0]), "r"(a[1]), "r"(a[2]), "r"(a[3]), "r"(b[0]), "r"(b[1]));
}
__device__ __forceinline__ void ldsm4(uint32_t* r, uint32_t addr) {
    asm volatile("ldmatrix.sync.aligned.m8n8.x4.shared.b16 {%0,%1,%2,%3}, [%4];"
                 : "=r"(r[0]), "=r"(r[1]), "=r"(r[2]), "=r"(r[3]) : "r"(addr));
}
__device__ __forceinline__ void ldsm4t(uint32_t* r, uint32_t addr) {
    asm volatile("ldmatrix.sync.aligned.m8n8.x4.trans.shared.b16 {%0,%1,%2,%3}, [%4];"
                 : "=r"(r[0]), "=r"(r[1]), "=r"(r[2]), "=r"(r[3]) : "r"(addr));
}
__device__ __forceinline__ void cp16(uint32_t dst, const void* src) {
    asm volatile("cp.async.cg.shared.global [%0], [%1], 16;\n" :: "r"(dst), "l"(src));
}
__device__ __forceinline__ void cp16z(uint32_t dst, const void* src, int srcbytes) {
    asm volatile("cp.async.cg.shared.global [%0], [%1], 16, %2;\n"
                 :: "r"(dst), "l"(src), "r"(srcbytes));
}
#define CP_COMMIT() asm volatile("cp.async.commit_group;\n")
#define CP_WAIT(n)  asm volatile("cp.async.wait_group %0;\n" :: "n"(n))

// ---------------------------------------------------------------------------
// batched fp32->fp16 conversion (one launch for all tensors)
// ---------------------------------------------------------------------------
#define NJOBS 9
struct F2HJobs {
    const float* src[NJOBS];
    __half* dst[NJOBS];
    int n8[NJOBS];
    int start[NJOBS + 1];
};

__global__ void f2h_all_kernel(F2HJobs jobs) {
    int bx = blockIdx.x;
    int j = 0;
    #pragma unroll
    for (int q = 0; q < NJOBS; q++)
        if (bx >= jobs.start[q + 1]) j = q + 1;
    int i = (bx - jobs.start[j]) * 256 + threadIdx.x;
    if (i >= jobs.n8[j]) return;
    const float4* s = (const float4*)jobs.src[j];
    float4 a = s[2 * i], b = s[2 * i + 1];
    __half2* d = (__half2*)jobs.dst[j];
    d[4 * i + 0] = __floats2half2_rn(a.x, a.y);
    d[4 * i + 1] = __floats2half2_rn(a.z, a.w);
    d[4 * i + 2] = __floats2half2_rn(b.x, b.y);
    d[4 * i + 3] = __floats2half2_rn(b.z, b.w);
}

__global__ void mean_kernel(const float* __restrict__ enc) {
    int b = blockIdx.x;
    int e = blockIdx.y * 256 + threadIdx.x;
    const float* base = enc + (size_t)b * PIX * ENCD + e;
    float s = 0.f;
    #pragma unroll 4
    for (int p = 0; p < PIX; p++) s += base[(size_t)p * ENCD];
    g_meanh[b * ENCD + e] = __float2half(s * (1.0f / PIX));
}

// ---------------------------------------------------------------------------
#define XSEL_H    0
#define XSEL_MEAN 1
#define XSEL_X    2

// M=64 fp16 GEMM via ldmatrix, split-K, N/K-concat. Tile 64x128, 2-stage.
__global__ void gemm64_h(int xsel, int ldx,
                         const __half* __restrict__ Wa, int lda, int na,
                         const __half* __restrict__ Wb, int ldb,
                         int rows1, const __half* __restrict__ W2k,
                         int N, int KS)
{
    __shared__ __align__(16) __half As[2][64 * 40];
    __shared__ __align__(16) __half Bs[2][32 * 136];
    const __half* X = (xsel == XSEL_H) ? g_hh : (xsel == XSEL_MEAN) ? g_meanh : g_xh;
    int n0 = blockIdx.x * 128;
    int s  = blockIdx.y;
    int tid = threadIdx.x;
    int lane = tid & 31, warp = tid >> 5;
    int wm = warp >> 2, wn = warp & 3;
    int g = lane >> 2, t4 = lane & 3;

    const __half* Wsel; int ld, coloff;
    if (n0 < na) { Wsel = Wa; ld = lda; coloff = n0; }
    else         { Wsel = Wb; ld = ldb; coloff = n0 - na; }

    float acc[2][4][4];
    #pragma unroll
    for (int i = 0; i < 2; i++)
        #pragma unroll
        for (int j = 0; j < 4; j++)
            #pragma unroll
            for (int q = 0; q < 4; q++) acc[i][j][q] = 0.f;

    int ar = tid >> 2, ak = (tid & 3) * 8;
    int bk = tid >> 3, bn = (tid & 7) * 16;
    int lrow = (lane & 7) + ((lane & 8) ? 8 : 0);
    int lcol = (lane & 16) ? 8 : 0;
    uint32_t asw[2], bsw[2], asb[2], bsb[2];
    #pragma unroll
    for (int u = 0; u < 2; u++) {
        asw[u] = (uint32_t)__cvta_generic_to_shared(&As[u][0]);
        bsw[u] = (uint32_t)__cvta_generic_to_shared(&Bs[u][0]);
        asb[u] = asw[u] + (ar * 40 + ak) * 2;
        bsb[u] = bsw[u] + (bk * 136 + bn) * 2;
    }
    int NC = KS / 32;

    auto issue = [&](int c, int buf) {
        int kbase = s * KS + c * 32;
        cp16(asb[buf], X + (size_t)ar * ldx + kbase + ak);
        int kg = kbase + bk;
        const __half* wrow = (kg < rows1)
            ? (Wsel + (size_t)kg * ld + coloff)
            : (W2k + (size_t)(kg - rows1) * ld + coloff);
        cp16(bsb[buf], wrow + bn);
        cp16(bsb[buf] + 16, wrow + bn + 8);
        CP_COMMIT();
    };

    issue(0, 0);
    for (int c = 0; c < NC; c++) {
        int buf = c & 1;
        if (c + 1 < NC) { issue(c + 1, buf ^ 1); CP_WAIT(1); }
        else            { CP_WAIT(0); }
        __syncthreads();
        #pragma unroll
        for (int kk = 0; kk < 32; kk += 16) {
            uint32_t afr[2][4], bfr[4][2];
            #pragma unroll
            for (int mt = 0; mt < 2; mt++) {
                int m = wm * 32 + mt * 16;
                ldsm4(afr[mt], asw[buf] + ((m + lrow) * 40 + kk + lcol) * 2);
            }
            #pragma unroll
            for (int nh = 0; nh < 2; nh++) {
                uint32_t br[4];
                int nb = wn * 32 + nh * 16;
                ldsm4t(br, bsw[buf] + ((kk + lrow) * 136 + nb + lcol) * 2);
                bfr[nh * 2 + 0][0] = br[0]; bfr[nh * 2 + 0][1] = br[1];
                bfr[nh * 2 + 1][0] = br[2]; bfr[nh * 2 + 1][1] = br[3];
            }
            #pragma unroll
            for (int mt = 0; mt < 2; mt++)
                #pragma unroll
                for (int nt = 0; nt < 4; nt++)
                    mma_f16(acc[mt][nt], afr[mt], bfr[nt]);
        }
        __syncthreads();
    }
    #pragma unroll
    for (int mt = 0; mt < 2; mt++) {
        int row = wm * 32 + mt * 16 + g;
        #pragma unroll
        for (int nt = 0; nt < 4; nt++) {
            int col = n0 + wn * 32 + nt * 8 + 2 * t4;
            float* p0 = g_part + (size_t)(s * BATCH + row) * N + col;
            p0[0] = acc[mt][nt][0]; p0[1] = acc[mt][nt][1];
            float* p1 = p0 + (size_t)8 * N;
            p1[0] = acc[mt][nt][2]; p1[1] = acc[mt][nt][3];
        }
    }
}

// finish h0/c0 from fused N=1024 GEMM partials
__global__ void finish_hc_kernel(const float* __restrict__ hb, const float* __restrict__ cb) {
    int b = blockIdx.x, d = threadIdx.x;   // 512 threads
    float vh = hb[d], vc = cb[d];
    for (int s = 0; s < 16; s++) {
        const float* pp = g_part + (size_t)(s * BATCH + b) * 1024;
        vh += pp[d];
        vc += pp[512 + d];
    }
    g_h[b * DECD + d] = vh;
    g_c[b * DECD + d] = vc;
    g_hh[b * DECD + d] = __float2half(vh);
}

// ---------------------------------------------------------------------------
// att1 (one-time): 12544x512 fp16 GEMM + bias -> fp16 g_att1h. Tile 128x128.
// ---------------------------------------------------------------------------
__global__ void att1_h(const __half* __restrict__ A, const __half* __restrict__ W,
                       const float* __restrict__ bias) {
    __shared__ __align__(16) __half As[2][128 * 40];
    __shared__ __align__(16) __half Bs[2][32 * 136];
    int m0 = blockIdx.x * 128, n0 = blockIdx.y * 128;
    int tid = threadIdx.x;
    int lane = tid & 31, warp = tid >> 5;
    int wm = warp >> 2, wn = warp & 3;
    int g = lane >> 2, t4 = lane & 3;

    float acc[4][4][4];
    #pragma unroll
    for (int i = 0; i < 4; i++)
        #pragma unroll
        for (int j = 0; j < 4; j++)
            #pragma unroll
            for (int q = 0; q < 4; q++) acc[i][j][q] = 0.f;

    int ar = tid >> 1, ak = (tid & 1) * 16;
    int bk = tid >> 3, bn = (tid & 7) * 16;
    int lrow = (lane & 7) + ((lane & 8) ? 8 : 0);
    int lcol = (lane & 16) ? 8 : 0;
    uint32_t asw[2], bsw[2], asb[2], bsb[2];
    #pragma unroll
    for (int u = 0; u < 2; u++) {
        asw[u] = (uint32_t)__cvta_generic_to_shared(&As[u][0]);
        bsw[u] = (uint32_t)__cvta_generic_to_shared(&Bs[u][0]);
        asb[u] = asw[u] + (ar * 40 + ak) * 2;
        bsb[u] = bsw[u] + (bk * 136 + bn) * 2;
    }
    const int NC = ENCD / 32;

    auto issue = [&](int c, int buf) {
        int kbase = c * 32;
        const __half* ap = A + (size_t)(m0 + ar) * ENCD + kbase + ak;
        cp16(asb[buf], ap);
        cp16(asb[buf] + 16, ap + 8);
        const __half* wrow = W + (size_t)(kbase + bk) * ATTD + n0 + bn;
        cp16(bsb[buf], wrow);
        cp16(bsb[buf] + 16, wrow + 8);
        CP_COMMIT();
    };

    issue(0, 0);
    for (int c = 0; c < NC; c++) {
        int buf = c & 1;
        if (c + 1 < NC) { issue(c + 1, buf ^ 1); CP_WAIT(1); }
        else            { CP_WAIT(0); }
        __syncthreads();
        #pragma unroll
        for (int kk = 0; kk < 32; kk += 16) {
            uint32_t afr[4][4], bfr[4][2];
            #pragma unroll
            for (int mt = 0; mt < 4; mt++) {
                int m = wm * 64 + mt * 16;
                ldsm4(afr[mt], asw[buf] + ((m + lrow) * 40 + kk + lcol) * 2);
            }
            #pragma unroll
            for (int nh = 0; nh < 2; nh++) {
                uint32_t br[4];
                int nb = wn * 32 + nh * 16;
                ldsm4t(br, bsw[buf] + ((kk + lrow) * 136 + nb + lcol) * 2);
                bfr[nh * 2 + 0][0] = br[0]; bfr[nh * 2 + 0][1] = br[1];
                bfr[nh * 2 + 1][0] = br[2]; bfr[nh * 2 + 1][1] = br[3];
            }
            #pragma unroll
            for (int mt = 0; mt < 4; mt++)
                #pragma unroll
                for (int nt = 0; nt < 4; nt++)
                    mma_f16(acc[mt][nt], afr[mt], bfr[nt]);
        }
        __syncthreads();
    }
    #pragma unroll
    for (int mt = 0; mt < 4; mt++) {
        int row = m0 + wm * 64 + mt * 16 + g;
        #pragma unroll
        for (int nt = 0; nt < 4; nt++) {
            int col = n0 + wn * 32 + nt * 8 + 2 * t4;
            float b0 = bias[col], b1 = bias[col + 1];
            __half2* p0 = (__half2*)(g_att1h + (size_t)row * ATTD) + (col >> 1);
            *p0 = __floats2half2_rn(acc[mt][nt][0] + b0, acc[mt][nt][1] + b1);
            __half2* p1 = (__half2*)(g_att1h + (size_t)(row + 8) * ATTD) + (col >> 1);
            *p1 = __floats2half2_rn(acc[mt][nt][2] + b0, acc[mt][nt][3] + b1);
        }
    }
}

// ---------------------------------------------------------------------------
// fc (deferred): 1344x20000 fp16 GEMM, masked epilogue. Tile 128x128.
// ---------------------------------------------------------------------------
__global__ void fc_h(const __half* __restrict__ W, const float* __restrict__ bias,
                     const int* __restrict__ lengths, float* __restrict__ out) {
    __shared__ __align__(16) __half As[2][128 * 40];
    __shared__ __align__(16) __half Bs[2][32 * 136];
    int n0 = blockIdx.x * 128, m0 = blockIdx.y * 128;
    int tid = threadIdx.x;
    int lane = tid & 31, warp = tid >> 5;
    int wm = warp >> 2, wn = warp & 3;
    int g = lane >> 2, t4 = lane & 3;
    bool full = (n0 + 128 <= VOCAB);

    float acc[4][4][4];
    #pragma unroll
    for (int i = 0; i < 4; i++)
        #pragma unroll
        for (int j = 0; j < 4; j++)
            #pragma unroll
            for (int q = 0; q < 4; q++) acc[i][j][q] = 0.f;

    int ar = tid >> 1, ak = (tid & 1) * 16;
    int bk = tid >> 3, bn = (tid & 7) * 16;
    int lrow = (lane & 7) + ((lane & 8) ? 8 : 0);
    int lcol = (lane & 16) ? 8 : 0;
    uint32_t asw[2], bsw[2], asb[2], bsb[2];
    #pragma unroll
    for (int u = 0; u < 2; u++) {
        asw[u] = (uint32_t)__cvta_generic_to_shared(&As[u][0]);
        bsw[u] = (uint32_t)__cvta_generic_to_shared(&Bs[u][0]);
        asb[u] = asw[u] + (ar * 40 + ak) * 2;
        bsb[u] = bsw[u] + (bk * 136 + bn) * 2;
    }
    const int NC = DECD / 32;

    auto issue = [&](int c, int buf) {
        int kbase = c * 32;
        const __half* ap = g_hallh + (size_t)(m0 + ar) * DECD + kbase + ak;
        cp16(asb[buf], ap);
        cp16(asb[buf] + 16, ap + 8);
        const __half* wrow = W + (size_t)(kbase + bk) * VOCAB + n0 + bn;
        if (full) {
            cp16(bsb[buf], wrow);
            cp16(bsb[buf] + 16, wrow + 8);
        } else {
            #pragma unroll
            for (int j = 0; j < 2; j++) {
                int col = n0 + bn + j * 8;
                int vb = (VOCAB - col) * 2;
                vb = vb < 0 ? 0 : (vb > 16 ? 16 : vb);
                cp16z(bsb[buf] + j * 16, wrow + j * 8, vb);
            }
        }
        CP_COMMIT();
    };

    issue(0, 0);
    for (int c = 0; c < NC; c++) {
        int buf = c & 1;
        if (c + 1 < NC) { issue(c + 1, buf ^ 1); CP_WAIT(1); }
        else            { CP_WAIT(0); }
        __syncthreads();
        #pragma unroll
        for (int kk = 0; kk < 32; kk += 16) {
            uint32_t afr[4][4], bfr[4][2];
            #pragma unroll
            for (int mt = 0; mt < 4; mt++) {
                int m = wm * 64 + mt * 16;
                ldsm4(afr[mt], asw[buf] + ((m + lrow) * 40 + kk + lcol) * 2);
            }
            #pragma unroll
            for (int nh = 0; nh < 2; nh++) {
                uint32_t br[4];
                int nb = wn * 32 + nh * 16;
                ldsm4t(br, bsw[buf] + ((kk + lrow) * 136 + nb + lcol) * 2);
                bfr[nh * 2 + 0][0] = br[0]; bfr[nh * 2 + 0][1] = br[1];
                bfr[nh * 2 + 1][0] = br[2]; bfr[nh * 2 + 1][1] = br[3];
            }
            #pragma unroll
            for (int mt = 0; mt < 4; mt++)
                #pragma unroll
                for (int nt = 0; nt < 4; nt++)
                    mma_f16(acc[mt][nt], afr[mt], bfr[nt]);
        }
        __syncthreads();
    }
    #pragma unroll
    for (int mt = 0; mt < 4; mt++) {
        int row = m0 + wm * 64 + mt * 16 + g;
        #pragma unroll
        for (int rh = 0; rh < 2; rh++) {
            int r = row + rh * 8;
            if (r >= TSTEP * BATCH) continue;
            int tt = r / BATCH, bb = r % BATCH;
            bool act = tt < (lengths[bb] - 1);
            float* orow = out + ((size_t)bb * TSTEP + tt) * VOCAB;
            #pragma unroll
            for (int nt = 0; nt < 4; nt++) {
                int col = n0 + wn * 32 + nt * 8 + 2 * t4;
                if (col < VOCAB)
                    orow[col] = act ? (acc[mt][nt][rh * 2 + 0] + bias[col]) : 0.f;
                if (col + 1 < VOCAB)
                    orow[col + 1] = act ? (acc[mt][nt][rh * 2 + 1] + bias[col + 1]) : 0.f;
            }
        }
    }
}

// ---------------------------------------------------------------------------
// scores (no softmax): grid (64, 2); block (b, p-half). fp16 att1 reads.
// ---------------------------------------------------------------------------
__global__ void scores_kernel(const float* __restrict__ dec_att_b,
                              const float* __restrict__ full_att_w,
                              const float* __restrict__ full_att_b, int nsplit) {
    __shared__ float2 att2p[ATTD / 2];
    __shared__ float2 fwp[ATTD / 2];
    int b = blockIdx.x, hf = blockIdx.y, tid = threadIdx.x;

    {
        int a2 = tid;
        float v0 = dec_att_b[2 * a2], v1 = dec_att_b[2 * a2 + 1];
        for (int s = 0; s < nsplit; s++) {
            const float2* pp = (const float2*)(g_part + (size_t)(s * BATCH + b) * 2560);
            float2 w = pp[a2];
            v0 += w.x; v1 += w.y;
        }
        att2p[a2] = make_float2(v0, v1);
        fwp[a2] = make_float2(full_att_w[2 * a2], full_att_w[2 * a2 + 1]);
    }
    __syncthreads();

    int warp = tid >> 5, lane = tid & 31;
    float fb = full_att_b[0];
    int p0 = hf * 98;
    int pend = p0 + 98;
    if (pend > PIX) pend = PIX;
    for (int p = p0 + warp; p < pend; p += 8) {
        const __half2* arow = (const __half2*)(g_att1h + ((size_t)(b * PIX + p)) * ATTD);
        float s = 0.f;
        #pragma unroll
        for (int i = 0; i < 8; i++) {
            int a2 = lane + i * 32;
            float2 v = __half22float2(arow[a2]);
            float2 w = att2p[a2];
            float2 fw = fwp[a2];
            s += fmaxf(v.x + w.x, 0.f) * fw.x + fmaxf(v.y + w.y, 0.f) * fw.y;
        }
        #pragma unroll
        for (int o = 16; o; o >>= 1) s += __shfl_xor_sync(~0u, s, o);
        if (!lane) g_scores[b * PIX + p] = s + fb;
    }
}

// ---------------------------------------------------------------------------
// softmax + alpha out + context (float4 enc loads) + gate -> g_xh ctx slot.
// grid (64), 256 threads; thread owns 8 consecutive e.  (R9-proven datapath)
// ---------------------------------------------------------------------------
__global__ void ctx_kernel(const float* __restrict__ f_beta_b,
                           const int* __restrict__ lengths,
                           float* __restrict__ out_alpha, int t, int nsplit) {
    __shared__ float als[PIX];
    __shared__ float red[8];
    int b = blockIdx.x, tid = threadIdx.x;
    int warp = tid >> 5, lane = tid & 31;

    // softmax over g_scores[b][:]
    float v = (tid < PIX) ? g_scores[b * PIX + tid] : -1e30f;
    float m = v;
    #pragma unroll
    for (int o = 16; o; o >>= 1) m = fmaxf(m, __shfl_xor_sync(~0u, m, o));
    if (!lane) red[warp] = m;
    __syncthreads();
    if (tid == 0) {
        float mm = red[0];
        for (int i = 1; i < 8; i++) mm = fmaxf(mm, red[i]);
        red[0] = mm;
    }
    __syncthreads();
    float mx = red[0];
    float e = (tid < PIX) ? __expf(v - mx) : 0.f;
    float s2 = e;
    #pragma unroll
    for (int o = 16; o; o >>= 1) s2 += __shfl_xor_sync(~0u, s2, o);
    __syncthreads();
    if (!lane) red[warp] = s2;
    __syncthreads();
    if (tid == 0) {
        float ss = 0.f;
        for (int i = 0; i < 8; i++) ss += red[i];
        red[0] = ss;
    }
    __syncthreads();
    float inv = 1.f / red[0];
    if (tid < PIX) {
        float al = e * inv;
        als[tid] = al;
        bool active = t < (lengths[b] - 1);
        out_alpha[((size_t)b * TSTEP + t) * PIX + tid] = active ? al : 0.f;
    }
    __syncthreads();

    // context: thread owns e = 8*tid .. 8*tid+7 (one float4 of halves per p)
    const float4* base = (const float4*)(g_ench + (size_t)b * PIX * ENCD) + tid;
    float c[8];
    #pragma unroll
    for (int j = 0; j < 8; j++) c[j] = 0.f;
    #pragma unroll 8
    for (int p = 0; p < PIX; p++) {
        float4 raw = base[(size_t)p * (ENCD / 8)];
        float al = als[p];
        const __half2* h = (const __half2*)&raw;
        #pragma unroll
        for (int j = 0; j < 4; j++) {
            float2 w = __half22float2(h[j]);
            c[2 * j + 0] += al * w.x;
            c[2 * j + 1] += al * w.y;
        }
    }
    // gate from attW partials cols [512, 2560)
    int e0 = 8 * tid;
    float gp[8];
    {
        const float4* fb4 = (const float4*)(f_beta_b + e0);
        float4 b0 = fb4[0], b1 = fb4[1];
        gp[0] = b0.x; gp[1] = b0.y; gp[2] = b0.z; gp[3] = b0.w;
        gp[4] = b1.x; gp[5] = b1.y; gp[6] = b1.z; gp[7] = b1.w;
    }
    for (int s = 0; s < nsplit; s++) {
        const float4* pp = (const float4*)(g_part + (size_t)(s * BATCH + b) * 2560 + 512 + e0);
        float4 q0 = pp[0], q1 = pp[1];
        gp[0] += q0.x; gp[1] += q0.y; gp[2] += q0.z; gp[3] += q0.w;
        gp[4] += q1.x; gp[5] += q1.y; gp[6] += q1.z; gp[7] += q1.w;
    }
    __half2 outh[4];
    #pragma unroll
    for (int j = 0; j < 4; j++) {
        float r0 = c[2 * j + 0] / (1.f + __expf(-gp[2 * j + 0]));
        float r1 = c[2 * j + 1] / (1.f + __expf(-gp[2 * j + 1]));
        outh[j] = __floats2half2_rn(r0, r1);
    }
    *((float4*)(g_xh + b * XDIM + EMBD + e0)) = *(const float4*)outh;
}

// ---------------------------------------------------------------------------
__global__ void init_x0_kernel(const float* __restrict__ emb,
                               const int* __restrict__ captions) {
    int b = blockIdx.x, d = threadIdx.x;
    int cap = captions[b * MAXLN];
    g_xh[b * XDIM + d] = __float2half(emb[(size_t)cap * EMBD + d]);
    g_xh[b * XDIM + EMBD + ENCD + d] = __float2half(g_h[b * DECD + d]);
}

__global__ void lstm_kernel(const float* __restrict__ b_ih, const float* __restrict__ b_hh,
                            const int* __restrict__ lengths,
                            const float* __restrict__ emb, const int* __restrict__ captions,
                            int t, int nsplit) {
    int b = blockIdx.x, d = threadIdx.x;
    float g4[4];
    #pragma unroll
    for (int gi = 0; gi < 4; gi++) {
        int n = gi * 512 + d;
        float v = b_ih[n] + b_hh[n];
        for (int s = 0; s < nsplit; s++) v += g_part[(size_t)(s * BATCH + b) * 2048 + n];
        g4[gi] = v;
    }
    float ig = 1.f / (1.f + __expf(-g4[0]));
    float fg = 1.f / (1.f + __expf(-g4[1]));
    float gg = tanhf(g4[2]);
    float og = 1.f / (1.f + __expf(-g4[3]));
    float cold = g_c[b * DECD + d];
    float cn = fg * cold + ig * gg;
    float hn = og * tanhf(cn);
    g_hallh[(size_t)(t * BATCH + b) * DECD + d] = __float2half(hn);
    bool act = t < (lengths[b] - 1);
    float hold = g_h[b * DECD + d];
    float hcur = act ? hn : hold;
    if (act) {
        g_h[b * DECD + d] = hn;
        g_c[b * DECD + d] = cn;
    }
    g_hh[b * DECD + d] = __float2half(hcur);
    if (t + 1 < TSTEP) {
        g_xh[b * XDIM + EMBD + ENCD + d] = __float2half(hcur);
        int cap = captions[b * MAXLN + t + 1];
        g_xh[b * XDIM + d] = __float2half(emb[(size_t)cap * EMBD + d]);
    }
}

// ---------------------------------------------------------------------------
extern "C" void kernel_launch(void* const* d_in, const int* in_sizes, int n_in,
                              void* d_out, int out_size) {
    const float* enc        = (const float*)d_in[0];
    const int*   captions   = (const int*)  d_in[1];
    const int*   lengths    = (const int*)  d_in[2];
    const float* emb        = (const float*)d_in[3];
    const float* enc_att_w  = (const float*)d_in[4];
    const float* enc_att_b  = (const float*)d_in[5];
    const float* dec_att_w  = (const float*)d_in[6];
    const float* dec_att_b  = (const float*)d_in[7];
    const float* full_att_w = (const float*)d_in[8];
    const float* full_att_b = (const float*)d_in[9];
    const float* w_ih       = (const float*)d_in[10];
    const float* b_ih       = (const float*)d_in[11];
    const float* w_hh       = (const float*)d_in[12];
    const float* b_hh       = (const float*)d_in[13];
    const float* init_h_w   = (const float*)d_in[14];
    const float* init_h_b   = (const float*)d_in[15];
    const float* init_c_w   = (const float*)d_in[16];
    const float* init_c_b   = (const float*)d_in[17];
    const float* f_beta_w   = (const float*)d_in[18];
    const float* f_beta_b   = (const float*)d_in[19];
    const float* fc_w       = (const float*)d_in[20];
    const float* fc_b       = (const float*)d_in[21];

    float* out       = (float*)d_out;
    float* out_alpha = out + (size_t)BATCH * TSTEP * VOCAB;

    __half *p_ench, *p_watt, *p_wfb, *p_wih, *p_whh, *p_wenc, *p_wh0, *p_wc0, *p_wfc;
    cudaGetSymbolAddress((void**)&p_ench, g_ench);
    cudaGetSymbolAddress((void**)&p_watt, g_w_att);
    cudaGetSymbolAddress((void**)&p_wfb,  g_w_fb);
    cudaGetSymbolAddress((void**)&p_wih,  g_w_ih);
    cudaGetSymbolAddress((void**)&p_whh,  g_w_hh);
    cudaGetSymbolAddress((void**)&p_wenc, g_w_enc);
    cudaGetSymbolAddress((void**)&p_wh0,  g_w_h0);
    cudaGetSymbolAddress((void**)&p_wc0,  g_w_c0);
    cudaGetSymbolAddress((void**)&p_wfc,  g_w_fc);

    // ---- single batched conversion launch ----
    F2HJobs jobs;
    const float* srcs[NJOBS] = { enc, dec_att_w, f_beta_w, w_ih, w_hh,
                                 enc_att_w, init_h_w, init_c_w, fc_w };
    __half* dsts[NJOBS] = { p_ench, p_watt, p_wfb, p_wih, p_whh,
                            p_wenc, p_wh0, p_wc0, p_wfc };
    int ns[NJOBS] = { BATCH * PIX * ENCD, ATTD * ATTD, DECD * ENCD,
                      (EMBD + ENCD) * 2048, DECD * 2048, ENCD * ATTD,
                      ENCD * DECD, ENCD * DECD, DECD * VOCAB };
    int acc = 0;
    for (int j = 0; j < NJOBS; j++) {
        jobs.src[j] = srcs[j];
        jobs.dst[j] = dsts[j];
        jobs.n8[j] = ns[j] / 8;
        jobs.start[j] = acc;
        acc += (jobs.n8[j] + 255) / 256;
    }
    jobs.start[NJOBS] = acc;
    f2h_all_kernel<<<acc, 256>>>(jobs);

    // ---- setup ----
    mean_kernel<<<dim3(BATCH, ENCD / 256), 256>>>(enc);
    // fused h0|c0: N=1024 = [init_h_w | init_c_w], K=2048 split 16
    gemm64_h<<<dim3(8, 16), 256>>>(XSEL_MEAN, ENCD, p_wh0, DECD, DECD,
                                   p_wc0, DECD, 1 << 30, nullptr, 1024, 128);
    finish_hc_kernel<<<BATCH, 512>>>(init_h_b, init_c_b);
    init_x0_kernel<<<BATCH, 512>>>(emb, captions);
    att1_h<<<dim3((BATCH * PIX) / 128, ATTD / 128), 256>>>(p_ench, p_wenc, enc_att_b);

    // ---- decode (R9 structure, verbatim) ----
    for (int t = 0; t < TSTEP; t++) {
        gemm64_h<<<dim3(20, 4), 256>>>(XSEL_H, DECD, p_watt, ATTD, ATTD,
                                       p_wfb, ENCD, DECD, nullptr, 2560, 128);
        scores_kernel<<<dim3(BATCH, 2), 256>>>(dec_att_b, full_att_w, full_att_b, 4);
        ctx_kernel<<<BATCH, 256>>>(f_beta_b, lengths, out_alpha, t, 4);
        gemm64_h<<<dim3(16, 8), 256>>>(XSEL_X, XDIM, p_wih, 2048, 2048,
                                       nullptr, 0, EMBD + ENCD, p_whh, 2048, 384);
        lstm_kernel<<<BATCH, 512>>>(b_ih, b_hh, lengths, emb, captions, t, 8);
    }

    // ---- deferred fc ----
    fc_h<<<dim3((VOCAB + 127) / 128, MROWS / 128), 256>>>(p_wfc, fc_b, lengths, out);
}

// round 13
// speedup vs baseline: 1.0501x; 1.0501x over previous
#include <cuda_runtime.h>
#include <cuda_fp16.h>
#include <cstdint>
#include <cstddef>

#define BATCH 64
#define PIX   196
#define ENCD  2048
#define ATTD  512
#define EMBD  512
#define DECD  512
#define VOCAB 20000
#define MAXLN 22
#define TSTEP 21
#define XDIM  3072
#define MROWS 1408   // 11*128 >= 21*64=1344

// ---------------- fp32 scratch ----------------
__device__ float g_h[BATCH * DECD];
__device__ float g_c[BATCH * DECD];
__device__ float g_scores[BATCH * PIX];
__device__ __align__(16) float g_part[16 * BATCH * 2560];

// ---------------- fp16 activations ----------------
__device__ __align__(16) __half g_att1h[BATCH * PIX * ATTD];
__device__ __align__(16) __half g_ench[BATCH * PIX * ENCD];
__device__ __align__(16) __half g_meanh[BATCH * ENCD];
__device__ __align__(16) __half g_hh[BATCH * DECD];
__device__ __align__(16) __half g_xh[BATCH * XDIM];
__device__ __align__(16) __half g_hallh[MROWS * DECD];

// ---------------- fp16 weights ----------------
__device__ __align__(16) __half g_w_att[ATTD * ATTD];
__device__ __align__(16) __half g_w_fb[DECD * ENCD];
__device__ __align__(16) __half g_w_ih[(EMBD + ENCD) * 2048];
__device__ __align__(16) __half g_w_hh[DECD * 2048];
__device__ __align__(16) __half g_w_enc[ENCD * ATTD];
__device__ __align__(16) __half g_w_h0[ENCD * DECD];
__device__ __align__(16) __half g_w_c0[ENCD * DECD];
__device__ __align__(16) __half g_w_fc[DECD * VOCAB];

// ---------------------------------------------------------------------------
__device__ __forceinline__ void mma_f16(float* d, const uint32_t* a, const uint32_t* b) {
    asm volatile(
        "mma.sync.aligned.m16n8k16.row.col.f32.f16.f16.f32 "
        "{%0,%1,%2,%3}, {%4,%5,%6,%7}, {%8,%9}, {%0,%1,%2,%3};\n"
        : "+f"(d[0]), "+f"(d[1]), "+f"(d[2]), "+f"(d[3])
        : "r"(a[0]), "r"(a[1]), "r"(a[2]), "r"(a[3]), "r"(b[0]), "r"(b[1]));
}
__device__ __forceinline__ void ldsm4(uint32_t* r, uint32_t addr) {
    asm volatile("ldmatrix.sync.aligned.m8n8.x4.shared.b16 {%0,%1,%2,%3}, [%4];"
                 : "=r"(r[0]), "=r"(r[1]), "=r"(r[2]), "=r"(r[3]) : "r"(addr));
}
__device__ __forceinline__ void ldsm4t(uint32_t* r, uint32_t addr) {
    asm volatile("ldmatrix.sync.aligned.m8n8.x4.trans.shared.b16 {%0,%1,%2,%3}, [%4];"
                 : "=r"(r[0]), "=r"(r[1]), "=r"(r[2]), "=r"(r[3]) : "r"(addr));
}
__device__ __forceinline__ void cp16(uint32_t dst, const void* src) {
    asm volatile("cp.async.cg.shared.global [%0], [%1], 16;\n" :: "r"(dst), "l"(src));
}
__device__ __forceinline__ void cp16z(uint32_t dst, const void* src, int srcbytes) {
    asm volatile("cp.async.cg.shared.global [%0], [%1], 16, %2;\n"
                 :: "r"(dst), "l"(src), "r"(srcbytes));
}
#define CP_COMMIT() asm volatile("cp.async.commit_group;\n")
#define CP_WAIT(n)  asm volatile("cp.async.wait_group %0;\n" :: "n"(n))

// ---------------------------------------------------------------------------
__global__ void f2h_kernel(const float* __restrict__ src, __half* __restrict__ dst, int n8) {
    int i = blockIdx.x * 256 + threadIdx.x;
    if (i >= n8) return;
    const float4* s = (const float4*)src;
    float4 a = s[2 * i], b = s[2 * i + 1];
    __half2* d = (__half2*)dst;
    d[4 * i + 0] = __floats2half2_rn(a.x, a.y);
    d[4 * i + 1] = __floats2half2_rn(a.z, a.w);
    d[4 * i + 2] = __floats2half2_rn(b.x, b.y);
    d[4 * i + 3] = __floats2half2_rn(b.z, b.w);
}

__global__ void mean_kernel(const float* __restrict__ enc) {
    int b = blockIdx.x;
    int e = blockIdx.y * 256 + threadIdx.x;
    const float* base = enc + (size_t)b * PIX * ENCD + e;
    float s = 0.f;
    #pragma unroll 4
    for (int p = 0; p < PIX; p++) s += base[(size_t)p * ENCD];
    g_meanh[b * ENCD + e] = __float2half(s * (1.0f / PIX));
}

// ---------------------------------------------------------------------------
#define XSEL_H    0
#define XSEL_MEAN 1
#define XSEL_X    2

// M=64 fp16 GEMM via ldmatrix, split-K, N/K-concat. Tile 64x128, 2-stage.
__global__ void gemm64_h(int xsel, int ldx,
                         const __half* __restrict__ Wa, int lda, int na,
                         const __half* __restrict__ Wb, int ldb,
                         int rows1, const __half* __restrict__ W2k,
                         int N, int KS)
{
    __shared__ __align__(16) __half As[2][64 * 40];
    __shared__ __align__(16) __half Bs[2][32 * 136];
    const __half* X = (xsel == XSEL_H) ? g_hh : (xsel == XSEL_MEAN) ? g_meanh : g_xh;
    int n0 = blockIdx.x * 128;
    int s  = blockIdx.y;
    int tid = threadIdx.x;
    int lane = tid & 31, warp = tid >> 5;
    int wm = warp >> 2, wn = warp & 3;
    int g = lane >> 2, t4 = lane & 3;

    const __half* Wsel; int ld, coloff;
    if (n0 < na) { Wsel = Wa; ld = lda; coloff = n0; }
    else         { Wsel = Wb; ld = ldb; coloff = n0 - na; }

    float acc[2][4][4];
    #pragma unroll
    for (int i = 0; i < 2; i++)
        #pragma unroll
        for (int j = 0; j < 4; j++)
            #pragma unroll
            for (int q = 0; q < 4; q++) acc[i][j][q] = 0.f;

    int ar = tid >> 2, ak = (tid & 3) * 8;
    int bk = tid >> 3, bn = (tid & 7) * 16;
    int lrow = (lane & 7) + ((lane & 8) ? 8 : 0);
    int lcol = (lane & 16) ? 8 : 0;
    uint32_t asw[2], bsw[2], asb[2], bsb[2];
    #pragma unroll
    for (int u = 0; u < 2; u++) {
        asw[u] = (uint32_t)__cvta_generic_to_shared(&As[u][0]);
        bsw[u] = (uint32_t)__cvta_generic_to_shared(&Bs[u][0]);
        asb[u] = asw[u] + (ar * 40 + ak) * 2;
        bsb[u] = bsw[u] + (bk * 136 + bn) * 2;
    }
    int NC = KS / 32;

    auto issue = [&](int c, int buf) {
        int kbase = s * KS + c * 32;
        cp16(asb[buf], X + (size_t)ar * ldx + kbase + ak);
        int kg = kbase + bk;
        const __half* wrow = (kg < rows1)
            ? (Wsel + (size_t)kg * ld + coloff)
            : (W2k + (size_t)(kg - rows1) * ld + coloff);
        cp16(bsb[buf], wrow + bn);
        cp16(bsb[buf] + 16, wrow + bn + 8);
        CP_COMMIT();
    };

    issue(0, 0);
    for (int c = 0; c < NC; c++) {
        int buf = c & 1;
        if (c + 1 < NC) { issue(c + 1, buf ^ 1); CP_WAIT(1); }
        else            { CP_WAIT(0); }
        __syncthreads();
        #pragma unroll
        for (int kk = 0; kk < 32; kk += 16) {
            uint32_t afr[2][4], bfr[4][2];
            #pragma unroll
            for (int mt = 0; mt < 2; mt++) {
                int m = wm * 32 + mt * 16;
                ldsm4(afr[mt], asw[buf] + ((m + lrow) * 40 + kk + lcol) * 2);
            }
            #pragma unroll
            for (int nh = 0; nh < 2; nh++) {
                uint32_t br[4];
                int nb = wn * 32 + nh * 16;
                ldsm4t(br, bsw[buf] + ((kk + lrow) * 136 + nb + lcol) * 2);
                bfr[nh * 2 + 0][0] = br[0]; bfr[nh * 2 + 0][1] = br[1];
                bfr[nh * 2 + 1][0] = br[2]; bfr[nh * 2 + 1][1] = br[3];
            }
            #pragma unroll
            for (int mt = 0; mt < 2; mt++)
                #pragma unroll
                for (int nt = 0; nt < 4; nt++)
                    mma_f16(acc[mt][nt], afr[mt], bfr[nt]);
        }
        __syncthreads();
    }
    #pragma unroll
    for (int mt = 0; mt < 2; mt++) {
        int row = wm * 32 + mt * 16 + g;
        #pragma unroll
        for (int nt = 0; nt < 4; nt++) {
            int col = n0 + wn * 32 + nt * 8 + 2 * t4;
            float* p0 = g_part + (size_t)(s * BATCH + row) * N + col;
            p0[0] = acc[mt][nt][0]; p0[1] = acc[mt][nt][1];
            float* p1 = p0 + (size_t)8 * N;
            p1[0] = acc[mt][nt][2]; p1[1] = acc[mt][nt][3];
        }
    }
}

__global__ void finish64_kernel(int dsel, const float* __restrict__ bias, int N, int nsplit) {
    int b = blockIdx.x;
    for (int n = threadIdx.x; n < N; n += blockDim.x) {
        float v = bias[n];
        for (int s = 0; s < nsplit; s++) v += g_part[(size_t)(s * BATCH + b) * N + n];
        if (dsel) g_c[b * N + n] = v;
        else {
            g_h[b * N + n] = v;
            g_hh[b * N + n] = __float2half(v);
        }
    }
}

// ---------------------------------------------------------------------------
// att1 (one-time): 12544x512 fp16 GEMM + bias -> fp16 g_att1h. Tile 128x128.
// ---------------------------------------------------------------------------
__global__ void att1_h(const __half* __restrict__ A, const __half* __restrict__ W,
                       const float* __restrict__ bias) {
    __shared__ __align__(16) __half As[2][128 * 40];
    __shared__ __align__(16) __half Bs[2][32 * 136];
    int m0 = blockIdx.x * 128, n0 = blockIdx.y * 128;
    int tid = threadIdx.x;
    int lane = tid & 31, warp = tid >> 5;
    int wm = warp >> 2, wn = warp & 3;
    int g = lane >> 2, t4 = lane & 3;

    float acc[4][4][4];
    #pragma unroll
    for (int i = 0; i < 4; i++)
        #pragma unroll
        for (int j = 0; j < 4; j++)
            #pragma unroll
            for (int q = 0; q < 4; q++) acc[i][j][q] = 0.f;

    int ar = tid >> 1, ak = (tid & 1) * 16;
    int bk = tid >> 3, bn = (tid & 7) * 16;
    int lrow = (lane & 7) + ((lane & 8) ? 8 : 0);
    int lcol = (lane & 16) ? 8 : 0;
    uint32_t asw[2], bsw[2], asb[2], bsb[2];
    #pragma unroll
    for (int u = 0; u < 2; u++) {
        asw[u] = (uint32_t)__cvta_generic_to_shared(&As[u][0]);
        bsw[u] = (uint32_t)__cvta_generic_to_shared(&Bs[u][0]);
        asb[u] = asw[u] + (ar * 40 + ak) * 2;
        bsb[u] = bsw[u] + (bk * 136 + bn) * 2;
    }
    const int NC = ENCD / 32;

    auto issue = [&](int c, int buf) {
        int kbase = c * 32;
        const __half* ap = A + (size_t)(m0 + ar) * ENCD + kbase + ak;
        cp16(asb[buf], ap);
        cp16(asb[buf] + 16, ap + 8);
        const __half* wrow = W + (size_t)(kbase + bk) * ATTD + n0 + bn;
        cp16(bsb[buf], wrow);
        cp16(bsb[buf] + 16, wrow + 8);
        CP_COMMIT();
    };

    issue(0, 0);
    for (int c = 0; c < NC; c++) {
        int buf = c & 1;
        if (c + 1 < NC) { issue(c + 1, buf ^ 1); CP_WAIT(1); }
        else            { CP_WAIT(0); }
        __syncthreads();
        #pragma unroll
        for (int kk = 0; kk < 32; kk += 16) {
            uint32_t afr[4][4], bfr[4][2];
            #pragma unroll
            for (int mt = 0; mt < 4; mt++) {
                int m = wm * 64 + mt * 16;
                ldsm4(afr[mt], asw[buf] + ((m + lrow) * 40 + kk + lcol) * 2);
            }
            #pragma unroll
            for (int nh = 0; nh < 2; nh++) {
                uint32_t br[4];
                int nb = wn * 32 + nh * 16;
                ldsm4t(br, bsw[buf] + ((kk + lrow) * 136 + nb + lcol) * 2);
                bfr[nh * 2 + 0][0] = br[0]; bfr[nh * 2 + 0][1] = br[1];
                bfr[nh * 2 + 1][0] = br[2]; bfr[nh * 2 + 1][1] = br[3];
            }
            #pragma unroll
            for (int mt = 0; mt < 4; mt++)
                #pragma unroll
                for (int nt = 0; nt < 4; nt++)
                    mma_f16(acc[mt][nt], afr[mt], bfr[nt]);
        }
        __syncthreads();
    }
    #pragma unroll
    for (int mt = 0; mt < 4; mt++) {
        int row = m0 + wm * 64 + mt * 16 + g;
        #pragma unroll
        for (int nt = 0; nt < 4; nt++) {
            int col = n0 + wn * 32 + nt * 8 + 2 * t4;
            float b0 = bias[col], b1 = bias[col + 1];
            __half2* p0 = (__half2*)(g_att1h + (size_t)row * ATTD) + (col >> 1);
            *p0 = __floats2half2_rn(acc[mt][nt][0] + b0, acc[mt][nt][1] + b1);
            __half2* p1 = (__half2*)(g_att1h + (size_t)(row + 8) * ATTD) + (col >> 1);
            *p1 = __floats2half2_rn(acc[mt][nt][2] + b0, acc[mt][nt][3] + b1);
        }
    }
}

// ---------------------------------------------------------------------------
// fc (deferred): 1344x20000 fp16 GEMM, masked epilogue. Tile 128x128.
// ---------------------------------------------------------------------------
__global__ void fc_h(const __half* __restrict__ W, const float* __restrict__ bias,
                     const int* __restrict__ lengths, float* __restrict__ out) {
    __shared__ __align__(16) __half As[2][128 * 40];
    __shared__ __align__(16) __half Bs[2][32 * 136];
    int n0 = blockIdx.x * 128, m0 = blockIdx.y * 128;
    int tid = threadIdx.x;
    int lane = tid & 31, warp = tid >> 5;
    int wm = warp >> 2, wn = warp & 3;
    int g = lane >> 2, t4 = lane & 3;
    bool full = (n0 + 128 <= VOCAB);

    float acc[4][4][4];
    #pragma unroll
    for (int i = 0; i < 4; i++)
        #pragma unroll
        for (int j = 0; j < 4; j++)
            #pragma unroll
            for (int q = 0; q < 4; q++) acc[i][j][q] = 0.f;

    int ar = tid >> 1, ak = (tid & 1) * 16;
    int bk = tid >> 3, bn = (tid & 7) * 16;
    int lrow = (lane & 7) + ((lane & 8) ? 8 : 0);
    int lcol = (lane & 16) ? 8 : 0;
    uint32_t asw[2], bsw[2], asb[2], bsb[2];
    #pragma unroll
    for (int u = 0; u < 2; u++) {
        asw[u] = (uint32_t)__cvta_generic_to_shared(&As[u][0]);
        bsw[u] = (uint32_t)__cvta_generic_to_shared(&Bs[u][0]);
        asb[u] = asw[u] + (ar * 40 + ak) * 2;
        bsb[u] = bsw[u] + (bk * 136 + bn) * 2;
    }
    const int NC = DECD / 32;

    auto issue = [&](int c, int buf) {
        int kbase = c * 32;
        const __half* ap = g_hallh + (size_t)(m0 + ar) * DECD + kbase + ak;
        cp16(asb[buf], ap);
        cp16(asb[buf] + 16, ap + 8);
        const __half* wrow = W + (size_t)(kbase + bk) * VOCAB + n0 + bn;
        if (full) {
            cp16(bsb[buf], wrow);
            cp16(bsb[buf] + 16, wrow + 8);
        } else {
            #pragma unroll
            for (int j = 0; j < 2; j++) {
                int col = n0 + bn + j * 8;
                int vb = (VOCAB - col) * 2;
                vb = vb < 0 ? 0 : (vb > 16 ? 16 : vb);
                cp16z(bsb[buf] + j * 16, wrow + j * 8, vb);
            }
        }
        CP_COMMIT();
    };

    issue(0, 0);
    for (int c = 0; c < NC; c++) {
        int buf = c & 1;
        if (c + 1 < NC) { issue(c + 1, buf ^ 1); CP_WAIT(1); }
        else            { CP_WAIT(0); }
        __syncthreads();
        #pragma unroll
        for (int kk = 0; kk < 32; kk += 16) {
            uint32_t afr[4][4], bfr[4][2];
            #pragma unroll
            for (int mt = 0; mt < 4; mt++) {
                int m = wm * 64 + mt * 16;
                ldsm4(afr[mt], asw[buf] + ((m + lrow) * 40 + kk + lcol) * 2);
            }
            #pragma unroll
            for (int nh = 0; nh < 2; nh++) {
                uint32_t br[4];
                int nb = wn * 32 + nh * 16;
                ldsm4t(br, bsw[buf] + ((kk + lrow) * 136 + nb + lcol) * 2);
                bfr[nh * 2 + 0][0] = br[0]; bfr[nh * 2 + 0][1] = br[1];
                bfr[nh * 2 + 1][0] = br[2]; bfr[nh * 2 + 1][1] = br[3];
            }
            #pragma unroll
            for (int mt = 0; mt < 4; mt++)
                #pragma unroll
                for (int nt = 0; nt < 4; nt++)
                    mma_f16(acc[mt][nt], afr[mt], bfr[nt]);
        }
        __syncthreads();
    }
    #pragma unroll
    for (int mt = 0; mt < 4; mt++) {
        int row = m0 + wm * 64 + mt * 16 + g;
        #pragma unroll
        for (int rh = 0; rh < 2; rh++) {
            int r = row + rh * 8;
            if (r >= TSTEP * BATCH) continue;
            int tt = r / BATCH, bb = r % BATCH;
            bool act = tt < (lengths[bb] - 1);
            float* orow = out + ((size_t)bb * TSTEP + tt) * VOCAB;
            #pragma unroll
            for (int nt = 0; nt < 4; nt++) {
                int col = n0 + wn * 32 + nt * 8 + 2 * t4;
                if (col < VOCAB)
                    orow[col] = act ? (acc[mt][nt][rh * 2 + 0] + bias[col]) : 0.f;
                if (col + 1 < VOCAB)
                    orow[col + 1] = act ? (acc[mt][nt][rh * 2 + 1] + bias[col + 1]) : 0.f;
            }
        }
    }
}

// ---------------------------------------------------------------------------
// scores (no softmax): grid (64, 2); block (b, p-half). fp16 att1 reads.
// ---------------------------------------------------------------------------
__global__ void scores_kernel(const float* __restrict__ dec_att_b,
                              const float* __restrict__ full_att_w,
                              const float* __restrict__ full_att_b, int nsplit) {
    __shared__ float2 att2p[ATTD / 2];
    __shared__ float2 fwp[ATTD / 2];
    int b = blockIdx.x, hf = blockIdx.y, tid = threadIdx.x;

    {   // a2 = tid covers 0..255 exactly
        int a2 = tid;
        float v0 = dec_att_b[2 * a2], v1 = dec_att_b[2 * a2 + 1];
        for (int s = 0; s < nsplit; s++) {
            const float2* pp = (const float2*)(g_part + (size_t)(s * BATCH + b) * 2560);
            float2 w = pp[a2];
            v0 += w.x; v1 += w.y;
        }
        att2p[a2] = make_float2(v0, v1);
        fwp[a2] = make_float2(full_att_w[2 * a2], full_att_w[2 * a2 + 1]);
    }
    __syncthreads();

    int warp = tid >> 5, lane = tid & 31;
    float fb = full_att_b[0];
    int p0 = hf * 98;
    int pend = p0 + 98;
    if (pend > PIX) pend = PIX;
    for (int p = p0 + warp; p < pend; p += 8) {
        const __half2* arow = (const __half2*)(g_att1h + ((size_t)(b * PIX + p)) * ATTD);
        float s = 0.f;
        #pragma unroll
        for (int i = 0; i < 8; i++) {
            int a2 = lane + i * 32;
            float2 v = __half22float2(arow[a2]);
            float2 w = att2p[a2];
            float2 fw = fwp[a2];
            s += fmaxf(v.x + w.x, 0.f) * fw.x + fmaxf(v.y + w.y, 0.f) * fw.y;
        }
        #pragma unroll
        for (int o = 16; o; o >>= 1) s += __shfl_xor_sync(~0u, s, o);
        if (!lane) g_scores[b * PIX + p] = s + fb;
    }
}

// ---------------------------------------------------------------------------
// softmax + alpha out + context (float4 enc loads) + gate -> g_xh ctx slot.
// grid (64), 256 threads; thread owns 8 consecutive e.
// ---------------------------------------------------------------------------
__global__ void ctx_kernel(const float* __restrict__ f_beta_b,
                           const int* __restrict__ lengths,
                           float* __restrict__ out_alpha, int t, int nsplit) {
    __shared__ float als[PIX];
    __shared__ float red[8];
    int b = blockIdx.x, tid = threadIdx.x;
    int warp = tid >> 5, lane = tid & 31;

    // softmax over g_scores[b][:]
    float v = (tid < PIX) ? g_scores[b * PIX + tid] : -1e30f;
    float m = v;
    #pragma unroll
    for (int o = 16; o; o >>= 1) m = fmaxf(m, __shfl_xor_sync(~0u, m, o));
    if (!lane) red[warp] = m;
    __syncthreads();
    if (tid == 0) {
        float mm = red[0];
        for (int i = 1; i < 8; i++) mm = fmaxf(mm, red[i]);
        red[0] = mm;
    }
    __syncthreads();
    float mx = red[0];
    float e = (tid < PIX) ? __expf(v - mx) : 0.f;
    float s2 = e;
    #pragma unroll
    for (int o = 16; o; o >>= 1) s2 += __shfl_xor_sync(~0u, s2, o);
    __syncthreads();
    if (!lane) red[warp] = s2;
    __syncthreads();
    if (tid == 0) {
        float ss = 0.f;
        for (int i = 0; i < 8; i++) ss += red[i];
        red[0] = ss;
    }
    __syncthreads();
    float inv = 1.f / red[0];
    if (tid < PIX) {
        float al = e * inv;
        als[tid] = al;
        bool active = t < (lengths[b] - 1);
        out_alpha[((size_t)b * TSTEP + t) * PIX + tid] = active ? al : 0.f;
    }
    __syncthreads();

    // context: thread owns e = 8*tid .. 8*tid+7 (one float4 of halves per p)
    const float4* base = (const float4*)(g_ench + (size_t)b * PIX * ENCD) + tid;
    float c[8];
    #pragma unroll
    for (int j = 0; j < 8; j++) c[j] = 0.f;
    #pragma unroll 8
    for (int p = 0; p < PIX; p++) {
        float4 raw = base[(size_t)p * (ENCD / 8)];
        float al = als[p];
        const __half2* h = (const __half2*)&raw;
        #pragma unroll
        for (int j = 0; j < 4; j++) {
            float2 w = __half22float2(h[j]);
            c[2 * j + 0] += al * w.x;
            c[2 * j + 1] += al * w.y;
        }
    }
    // gate from attW partials cols [512, 2560)
    int e0 = 8 * tid;
    float gp[8];
    {
        const float4* fb4 = (const float4*)(f_beta_b + e0);
        float4 b0 = fb4[0], b1 = fb4[1];
        gp[0] = b0.x; gp[1] = b0.y; gp[2] = b0.z; gp[3] = b0.w;
        gp[4] = b1.x; gp[5] = b1.y; gp[6] = b1.z; gp[7] = b1.w;
    }
    for (int s = 0; s < nsplit; s++) {
        const float4* pp = (const float4*)(g_part + (size_t)(s * BATCH + b) * 2560 + 512 + e0);
        float4 q0 = pp[0], q1 = pp[1];
        gp[0] += q0.x; gp[1] += q0.y; gp[2] += q0.z; gp[3] += q0.w;
        gp[4] += q1.x; gp[5] += q1.y; gp[6] += q1.z; gp[7] += q1.w;
    }
    __half2 outh[4];
    #pragma unroll
    for (int j = 0; j < 4; j++) {
        float r0 = c[2 * j + 0] / (1.f + __expf(-gp[2 * j + 0]));
        float r1 = c[2 * j + 1] / (1.f + __expf(-gp[2 * j + 1]));
        outh[j] = __floats2half2_rn(r0, r1);
    }
    *((float4*)(g_xh + b * XDIM + EMBD + e0)) = *(const float4*)outh;
}

// ---------------------------------------------------------------------------
__global__ void init_x0_kernel(const float* __restrict__ emb,
                               const int* __restrict__ captions) {
    int b = blockIdx.x, d = threadIdx.x;
    int cap = captions[b * MAXLN];
    g_xh[b * XDIM + d] = __float2half(emb[(size_t)cap * EMBD + d]);
    g_xh[b * XDIM + EMBD + ENCD + d] = __float2half(g_h[b * DECD + d]);
}

__global__ void lstm_kernel(const float* __restrict__ b_ih, const float* __restrict__ b_hh,
                            const int* __restrict__ lengths,
                            const float* __restrict__ emb, const int* __restrict__ captions,
                            int t, int nsplit) {
    int b = blockIdx.x, d = threadIdx.x;
    float g4[4];
    #pragma unroll
    for (int gi = 0; gi < 4; gi++) {
        int n = gi * 512 + d;
        float v = b_ih[n] + b_hh[n];
        for (int s = 0; s < nsplit; s++) v += g_part[(size_t)(s * BATCH + b) * 2048 + n];
        g4[gi] = v;
    }
    float ig = 1.f / (1.f + __expf(-g4[0]));
    float fg = 1.f / (1.f + __expf(-g4[1]));
    float gg = tanhf(g4[2]);
    float og = 1.f / (1.f + __expf(-g4[3]));
    float cold = g_c[b * DECD + d];
    float cn = fg * cold + ig * gg;
    float hn = og * tanhf(cn);
    g_hallh[(size_t)(t * BATCH + b) * DECD + d] = __float2half(hn);
    bool act = t < (lengths[b] - 1);
    float hold = g_h[b * DECD + d];
    float hcur = act ? hn : hold;
    if (act) {
        g_h[b * DECD + d] = hn;
        g_c[b * DECD + d] = cn;
    }
    g_hh[b * DECD + d] = __float2half(hcur);
    if (t + 1 < TSTEP) {
        g_xh[b * XDIM + EMBD + ENCD + d] = __float2half(hcur);
        int cap = captions[b * MAXLN + t + 1];
        g_xh[b * XDIM + d] = __float2half(emb[(size_t)cap * EMBD + d]);
    }
}

// ---------------------------------------------------------------------------
static void f2h(const float* src, __half* dst, int n) {
    int n8 = n / 8;
    f2h_kernel<<<(n8 + 255) / 256, 256>>>(src, dst, n8);
}

extern "C" void kernel_launch(void* const* d_in, const int* in_sizes, int n_in,
                              void* d_out, int out_size) {
    const float* enc        = (const float*)d_in[0];
    const int*   captions   = (const int*)  d_in[1];
    const int*   lengths    = (const int*)  d_in[2];
    const float* emb        = (const float*)d_in[3];
    const float* enc_att_w  = (const float*)d_in[4];
    const float* enc_att_b  = (const float*)d_in[5];
    const float* dec_att_w  = (const float*)d_in[6];
    const float* dec_att_b  = (const float*)d_in[7];
    const float* full_att_w = (const float*)d_in[8];
    const float* full_att_b = (const float*)d_in[9];
    const float* w_ih       = (const float*)d_in[10];
    const float* b_ih       = (const float*)d_in[11];
    const float* w_hh       = (const float*)d_in[12];
    const float* b_hh       = (const float*)d_in[13];
    const float* init_h_w   = (const float*)d_in[14];
    const float* init_h_b   = (const float*)d_in[15];
    const float* init_c_w   = (const float*)d_in[16];
    const float* init_c_b   = (const float*)d_in[17];
    const float* f_beta_w   = (const float*)d_in[18];
    const float* f_beta_b   = (const float*)d_in[19];
    const float* fc_w       = (const float*)d_in[20];
    const float* fc_b       = (const float*)d_in[21];

    float* out       = (float*)d_out;
    float* out_alpha = out + (size_t)BATCH * TSTEP * VOCAB;

    __half *p_ench, *p_watt, *p_wfb, *p_wih, *p_whh, *p_wenc, *p_wh0, *p_wc0, *p_wfc;
    cudaGetSymbolAddress((void**)&p_ench, g_ench);
    cudaGetSymbolAddress((void**)&p_watt, g_w_att);
    cudaGetSymbolAddress((void**)&p_wfb,  g_w_fb);
    cudaGetSymbolAddress((void**)&p_wih,  g_w_ih);
    cudaGetSymbolAddress((void**)&p_whh,  g_w_hh);
    cudaGetSymbolAddress((void**)&p_wenc, g_w_enc);
    cudaGetSymbolAddress((void**)&p_wh0,  g_w_h0);
    cudaGetSymbolAddress((void**)&p_wc0,  g_w_c0);
    cudaGetSymbolAddress((void**)&p_wfc,  g_w_fc);

    // ---- conversions ----
    f2h(enc,       p_ench, BATCH * PIX * ENCD);
    f2h(dec_att_w, p_watt, ATTD * ATTD);
    f2h(f_beta_w,  p_wfb,  DECD * ENCD);
    f2h(w_ih,      p_wih,  (EMBD + ENCD) * 2048);
    f2h(w_hh,      p_whh,  DECD * 2048);
    f2h(enc_att_w, p_wenc, ENCD * ATTD);
    f2h(init_h_w,  p_wh0,  ENCD * DECD);
    f2h(init_c_w,  p_wc0,  ENCD * DECD);
    f2h(fc_w,      p_wfc,  DECD * VOCAB);

    // ---- setup ----
    mean_kernel<<<dim3(BATCH, ENCD / 256), 256>>>(enc);
    gemm64_h<<<dim3(4, 16), 256>>>(XSEL_MEAN, ENCD, p_wh0, DECD, DECD,
                                   nullptr, 0, ENCD, nullptr, DECD, 128);
    finish64_kernel<<<BATCH, 512>>>(0, init_h_b, DECD, 16);
    gemm64_h<<<dim3(4, 16), 256>>>(XSEL_MEAN, ENCD, p_wc0, DECD, DECD,
                                   nullptr, 0, ENCD, nullptr, DECD, 128);
    finish64_kernel<<<BATCH, 512>>>(1, init_c_b, DECD, 16);
    init_x0_kernel<<<BATCH, 512>>>(emb, captions);
    att1_h<<<dim3((BATCH * PIX) / 128, ATTD / 128), 256>>>(p_ench, p_wenc, enc_att_b);

    // ---- decode ----
    for (int t = 0; t < TSTEP; t++) {
        gemm64_h<<<dim3(20, 4), 256>>>(XSEL_H, DECD, p_watt, ATTD, ATTD,
                                       p_wfb, ENCD, DECD, nullptr, 2560, 128);
        scores_kernel<<<dim3(BATCH, 2), 256>>>(dec_att_b, full_att_w, full_att_b, 4);
        ctx_kernel<<<BATCH, 256>>>(f_beta_b, lengths, out_alpha, t, 4);
        gemm64_h<<<dim3(16, 8), 256>>>(XSEL_X, XDIM, p_wih, 2048, 2048,
                                       nullptr, 0, EMBD + ENCD, p_whh, 2048, 384);
        lstm_kernel<<<BATCH, 512>>>(b_ih, b_hh, lengths, emb, captions, t, 8);
    }

    // ---- deferred fc ----
    fc_h<<<dim3((VOCAB + 127) / 128, MROWS / 128), 256>>>(p_wfc, fc_b, lengths, out);
}

// round 14
// speedup vs baseline: 1.2123x; 1.1544x over previous
#include <cuda_runtime.h>
#include <cuda_fp16.h>
#include <cstdint>
#include <cstddef>

#define BATCH 64
#define PIX   196
#define ENCD  2048
#define ATTD  512
#define EMBD  512
#define DECD  512
#define VOCAB 20000
#define MAXLN 22
#define TSTEP 21
#define XDIM  3072
#define MROWS 1408   // 11*128 >= 21*64=1344

// ---------------- fp32 scratch ----------------
__device__ float g_h[BATCH * DECD];
__device__ float g_c[BATCH * DECD];
__device__ __align__(16) float g_part[16 * BATCH * 2560];

// ---------------- fp16 activations ----------------
__device__ __align__(16) __half g_att1h[BATCH * PIX * ATTD];
__device__ __align__(16) __half g_ench[BATCH * PIX * ENCD];
__device__ __align__(16) __half g_meanh[BATCH * ENCD];
__device__ __align__(16) __half g_hh[BATCH * DECD];
__device__ __align__(16) __half g_xh[BATCH * XDIM];
__device__ __align__(16) __half g_hallh[MROWS * DECD];

// ---------------- fp16 weights ----------------
__device__ __align__(16) __half g_w_att[ATTD * ATTD];
__device__ __align__(16) __half g_w_fb[DECD * ENCD];
__device__ __align__(16) __half g_w_ih[(EMBD + ENCD) * 2048];
__device__ __align__(16) __half g_w_hh[DECD * 2048];
__device__ __align__(16) __half g_w_enc[ENCD * ATTD];
__device__ __align__(16) __half g_w_h0[ENCD * DECD];
__device__ __align__(16) __half g_w_c0[ENCD * DECD];
__device__ __align__(16) __half g_w_fc[DECD * VOCAB];

// ---------------------------------------------------------------------------
__device__ __forceinline__ void mma_f16(float* d, const uint32_t* a, const uint32_t* b) {
    asm volatile(
        "mma.sync.aligned.m16n8k16.row.col.f32.f16.f16.f32 "
        "{%0,%1,%2,%3}, {%4,%5,%6,%7}, {%8,%9}, {%0,%1,%2,%3};\n"
        : "+f"(d[0]), "+f"(d[1]), "+f"(d[2]), "+f"(d[3])
        : "r"(a[0]), "r"(a[1]), "r"(a[2]), "r"(a[3]), "r"(b[0]), "r"(b[1]));
}
__device__ __forceinline__ void ldsm4(uint32_t* r, uint32_t addr) {
    asm volatile("ldmatrix.sync.aligned.m8n8.x4.shared.b16 {%0,%1,%2,%3}, [%4];"
                 : "=r"(r[0]), "=r"(r[1]), "=r"(r[2]), "=r"(r[3]) : "r"(addr));
}
__device__ __forceinline__ void ldsm4t(uint32_t* r, uint32_t addr) {
    asm volatile("ldmatrix.sync.aligned.m8n8.x4.trans.shared.b16 {%0,%1,%2,%3}, [%4];"
                 : "=r"(r[0]), "=r"(r[1]), "=r"(r[2]), "=r"(r[3]) : "r"(addr));
}
__device__ __forceinline__ void cp16(uint32_t dst, const void* src) {
    asm volatile("cp.async.cg.shared.global [%0], [%1], 16;\n" :: "r"(dst), "l"(src));
}
__device__ __forceinline__ void cp16z(uint32_t dst, const void* src, int srcbytes) {
    asm volatile("cp.async.cg.shared.global [%0], [%1], 16, %2;\n"
                 :: "r"(dst), "l"(src), "r"(srcbytes));
}
#define CP_COMMIT() asm volatile("cp.async.commit_group;\n")
#define CP_WAIT(n)  asm volatile("cp.async.wait_group %0;\n" :: "n"(n))

// ---------------------------------------------------------------------------
// batched fp32->fp16 conversion (one launch for all tensors)
// ---------------------------------------------------------------------------
#define NJOBS 9
struct F2HJobs {
    const float* src[NJOBS];
    __half* dst[NJOBS];
    int n8[NJOBS];
    int start[NJOBS + 1];
};

__global__ void f2h_all_kernel(F2HJobs jobs) {
    int bx = blockIdx.x;
    int j = 0;
    #pragma unroll
    for (int q = 0; q < NJOBS; q++)
        if (bx >= jobs.start[q + 1]) j = q + 1;
    int i = (bx - jobs.start[j]) * 256 + threadIdx.x;
    if (i >= jobs.n8[j]) return;
    const float4* s = (const float4*)jobs.src[j];
    float4 a = s[2 * i], b = s[2 * i + 1];
    __half2* d = (__half2*)jobs.dst[j];
    d[4 * i + 0] = __floats2half2_rn(a.x, a.y);
    d[4 * i + 1] = __floats2half2_rn(a.z, a.w);
    d[4 * i + 2] = __floats2half2_rn(b.x, b.y);
    d[4 * i + 3] = __floats2half2_rn(b.z, b.w);
}

__global__ void mean_kernel(const float* __restrict__ enc) {
    int b = blockIdx.x;
    int e = blockIdx.y * 256 + threadIdx.x;
    const float* base = enc + (size_t)b * PIX * ENCD + e;
    float s = 0.f;
    #pragma unroll 4
    for (int p = 0; p < PIX; p++) s += base[(size_t)p * ENCD];
    g_meanh[b * ENCD + e] = __float2half(s * (1.0f / PIX));
}

// ---------------------------------------------------------------------------
#define XSEL_H    0
#define XSEL_MEAN 1
#define XSEL_X    2

// M=64 fp16 GEMM via ldmatrix, split-K, N/K-concat. Tile 64x128, 2-stage.
__global__ void gemm64_h(int xsel, int ldx,
                         const __half* __restrict__ Wa, int lda, int na,
                         const __half* __restrict__ Wb, int ldb,
                         int rows1, const __half* __restrict__ W2k,
                         int N, int KS)
{
    __shared__ __align__(16) __half As[2][64 * 40];
    __shared__ __align__(16) __half Bs[2][32 * 136];
    const __half* X = (xsel == XSEL_H) ? g_hh : (xsel == XSEL_MEAN) ? g_meanh : g_xh;
    int n0 = blockIdx.x * 128;
    int s  = blockIdx.y;
    int tid = threadIdx.x;
    int lane = tid & 31, warp = tid >> 5;
    int wm = warp >> 2, wn = warp & 3;
    int g = lane >> 2, t4 = lane & 3;

    const __half* Wsel; int ld, coloff;
    if (n0 < na) { Wsel = Wa; ld = lda; coloff = n0; }
    else         { Wsel = Wb; ld = ldb; coloff = n0 - na; }

    float acc[2][4][4];
    #pragma unroll
    for (int i = 0; i < 2; i++)
        #pragma unroll
        for (int j = 0; j < 4; j++)
            #pragma unroll
            for (int q = 0; q < 4; q++) acc[i][j][q] = 0.f;

    int ar = tid >> 2, ak = (tid & 3) * 8;
    int bk = tid >> 3, bn = (tid & 7) * 16;
    int lrow = (lane & 7) + ((lane & 8) ? 8 : 0);
    int lcol = (lane & 16) ? 8 : 0;
    uint32_t asw[2], bsw[2], asb[2], bsb[2];
    #pragma unroll
    for (int u = 0; u < 2; u++) {
        asw[u] = (uint32_t)__cvta_generic_to_shared(&As[u][0]);
        bsw[u] = (uint32_t)__cvta_generic_to_shared(&Bs[u][0]);
        asb[u] = asw[u] + (ar * 40 + ak) * 2;
        bsb[u] = bsw[u] + (bk * 136 + bn) * 2;
    }
    int NC = KS / 32;

    auto issue = [&](int c, int buf) {
        int kbase = s * KS + c * 32;
        cp16(asb[buf], X + (size_t)ar * ldx + kbase + ak);
        int kg = kbase + bk;
        const __half* wrow = (kg < rows1)
            ? (Wsel + (size_t)kg * ld + coloff)
            : (W2k + (size_t)(kg - rows1) * ld + coloff);
        cp16(bsb[buf], wrow + bn);
        cp16(bsb[buf] + 16, wrow + bn + 8);
        CP_COMMIT();
    };

    issue(0, 0);
    for (int c = 0; c < NC; c++) {
        int buf = c & 1;
        if (c + 1 < NC) { issue(c + 1, buf ^ 1); CP_WAIT(1); }
        else            { CP_WAIT(0); }
        __syncthreads();
        #pragma unroll
        for (int kk = 0; kk < 32; kk += 16) {
            uint32_t afr[2][4], bfr[4][2];
            #pragma unroll
            for (int mt = 0; mt < 2; mt++) {
                int m = wm * 32 + mt * 16;
                ldsm4(afr[mt], asw[buf] + ((m + lrow) * 40 + kk + lcol) * 2);
            }
            #pragma unroll
            for (int nh = 0; nh < 2; nh++) {
                uint32_t br[4];
                int nb = wn * 32 + nh * 16;
                ldsm4t(br, bsw[buf] + ((kk + lrow) * 136 + nb + lcol) * 2);
                bfr[nh * 2 + 0][0] = br[0]; bfr[nh * 2 + 0][1] = br[1];
                bfr[nh * 2 + 1][0] = br[2]; bfr[nh * 2 + 1][1] = br[3];
            }
            #pragma unroll
            for (int mt = 0; mt < 2; mt++)
                #pragma unroll
                for (int nt = 0; nt < 4; nt++)
                    mma_f16(acc[mt][nt], afr[mt], bfr[nt]);
        }
        __syncthreads();
    }
    #pragma unroll
    for (int mt = 0; mt < 2; mt++) {
        int row = wm * 32 + mt * 16 + g;
        #pragma unroll
        for (int nt = 0; nt < 4; nt++) {
            int col = n0 + wn * 32 + nt * 8 + 2 * t4;
            float* p0 = g_part + (size_t)(s * BATCH + row) * N + col;
            p0[0] = acc[mt][nt][0]; p0[1] = acc[mt][nt][1];
            float* p1 = p0 + (size_t)8 * N;
            p1[0] = acc[mt][nt][2]; p1[1] = acc[mt][nt][3];
        }
    }
}

// finish h0/c0 from fused N=1024 GEMM partials
__global__ void finish_hc_kernel(const float* __restrict__ hb, const float* __restrict__ cb) {
    int b = blockIdx.x, d = threadIdx.x;   // 512 threads
    float vh = hb[d], vc = cb[d];
    for (int s = 0; s < 16; s++) {
        const float* pp = g_part + (size_t)(s * BATCH + b) * 1024;
        vh += pp[d];
        vc += pp[512 + d];
    }
    g_h[b * DECD + d] = vh;
    g_c[b * DECD + d] = vc;
    g_hh[b * DECD + d] = __float2half(vh);
}

// ---------------------------------------------------------------------------
// att1 (one-time): 12544x512 fp16 GEMM + bias -> fp16 g_att1h. Tile 128x128.
// ---------------------------------------------------------------------------
__global__ void att1_h(const __half* __restrict__ A, const __half* __restrict__ W,
                       const float* __restrict__ bias) {
    __shared__ __align__(16) __half As[2][128 * 40];
    __shared__ __align__(16) __half Bs[2][32 * 136];
    int m0 = blockIdx.x * 128, n0 = blockIdx.y * 128;
    int tid = threadIdx.x;
    int lane = tid & 31, warp = tid >> 5;
    int wm = warp >> 2, wn = warp & 3;
    int g = lane >> 2, t4 = lane & 3;

    float acc[4][4][4];
    #pragma unroll
    for (int i = 0; i < 4; i++)
        #pragma unroll
        for (int j = 0; j < 4; j++)
            #pragma unroll
            for (int q = 0; q < 4; q++) acc[i][j][q] = 0.f;

    int ar = tid >> 1, ak = (tid & 1) * 16;
    int bk = tid >> 3, bn = (tid & 7) * 16;
    int lrow = (lane & 7) + ((lane & 8) ? 8 : 0);
    int lcol = (lane & 16) ? 8 : 0;
    uint32_t asw[2], bsw[2], asb[2], bsb[2];
    #pragma unroll
    for (int u = 0; u < 2; u++) {
        asw[u] = (uint32_t)__cvta_generic_to_shared(&As[u][0]);
        bsw[u] = (uint32_t)__cvta_generic_to_shared(&Bs[u][0]);
        asb[u] = asw[u] + (ar * 40 + ak) * 2;
        bsb[u] = bsw[u] + (bk * 136 + bn) * 2;
    }
    const int NC = ENCD / 32;

    auto issue = [&](int c, int buf) {
        int kbase = c * 32;
        const __half* ap = A + (size_t)(m0 + ar) * ENCD + kbase + ak;
        cp16(asb[buf], ap);
        cp16(asb[buf] + 16, ap + 8);
        const __half* wrow = W + (size_t)(kbase + bk) * ATTD + n0 + bn;
        cp16(bsb[buf], wrow);
        cp16(bsb[buf] + 16, wrow + 8);
        CP_COMMIT();
    };

    issue(0, 0);
    for (int c = 0; c < NC; c++) {
        int buf = c & 1;
        if (c + 1 < NC) { issue(c + 1, buf ^ 1); CP_WAIT(1); }
        else            { CP_WAIT(0); }
        __syncthreads();
        #pragma unroll
        for (int kk = 0; kk < 32; kk += 16) {
            uint32_t afr[4][4], bfr[4][2];
            #pragma unroll
            for (int mt = 0; mt < 4; mt++) {
                int m = wm * 64 + mt * 16;
                ldsm4(afr[mt], asw[buf] + ((m + lrow) * 40 + kk + lcol) * 2);
            }
            #pragma unroll
            for (int nh = 0; nh < 2; nh++) {
                uint32_t br[4];
                int nb = wn * 32 + nh * 16;
                ldsm4t(br, bsw[buf] + ((kk + lrow) * 136 + nb + lcol) * 2);
                bfr[nh * 2 + 0][0] = br[0]; bfr[nh * 2 + 0][1] = br[1];
                bfr[nh * 2 + 1][0] = br[2]; bfr[nh * 2 + 1][1] = br[3];
            }
            #pragma unroll
            for (int mt = 0; mt < 4; mt++)
                #pragma unroll
                for (int nt = 0; nt < 4; nt++)
                    mma_f16(acc[mt][nt], afr[mt], bfr[nt]);
        }
        __syncthreads();
    }
    #pragma unroll
    for (int mt = 0; mt < 4; mt++) {
        int row = m0 + wm * 64 + mt * 16 + g;
        #pragma unroll
        for (int nt = 0; nt < 4; nt++) {
            int col = n0 + wn * 32 + nt * 8 + 2 * t4;
            float b0 = bias[col], b1 = bias[col + 1];
            __half2* p0 = (__half2*)(g_att1h + (size_t)row * ATTD) + (col >> 1);
            *p0 = __floats2half2_rn(acc[mt][nt][0] + b0, acc[mt][nt][1] + b1);
            __half2* p1 = (__half2*)(g_att1h + (size_t)(row + 8) * ATTD) + (col >> 1);
            *p1 = __floats2half2_rn(acc[mt][nt][2] + b0, acc[mt][nt][3] + b1);
        }
    }
}

// ---------------------------------------------------------------------------
// fc (deferred): 1344x20000 fp16 GEMM, masked epilogue. Tile 128x128.
// ---------------------------------------------------------------------------
__global__ void fc_h(const __half* __restrict__ W, const float* __restrict__ bias,
                     const int* __restrict__ lengths, float* __restrict__ out) {
    __shared__ __align__(16) __half As[2][128 * 40];
    __shared__ __align__(16) __half Bs[2][32 * 136];
    int n0 = blockIdx.x * 128, m0 = blockIdx.y * 128;
    int tid = threadIdx.x;
    int lane = tid & 31, warp = tid >> 5;
    int wm = warp >> 2, wn = warp & 3;
    int g = lane >> 2, t4 = lane & 3;
    bool full = (n0 + 128 <= VOCAB);

    float acc[4][4][4];
    #pragma unroll
    for (int i = 0; i < 4; i++)
        #pragma unroll
        for (int j = 0; j < 4; j++)
            #pragma unroll
            for (int q = 0; q < 4; q++) acc[i][j][q] = 0.f;

    int ar = tid >> 1, ak = (tid & 1) * 16;
    int bk = tid >> 3, bn = (tid & 7) * 16;
    int lrow = (lane & 7) + ((lane & 8) ? 8 : 0);
    int lcol = (lane & 16) ? 8 : 0;
    uint32_t asw[2], bsw[2], asb[2], bsb[2];
    #pragma unroll
    for (int u = 0; u < 2; u++) {
        asw[u] = (uint32_t)__cvta_generic_to_shared(&As[u][0]);
        bsw[u] = (uint32_t)__cvta_generic_to_shared(&Bs[u][0]);
        asb[u] = asw[u] + (ar * 40 + ak) * 2;
        bsb[u] = bsw[u] + (bk * 136 + bn) * 2;
    }
    const int NC = DECD / 32;

    auto issue = [&](int c, int buf) {
        int kbase = c * 32;
        const __half* ap = g_hallh + (size_t)(m0 + ar) * DECD + kbase + ak;
        cp16(asb[buf], ap);
        cp16(asb[buf] + 16, ap + 8);
        const __half* wrow = W + (size_t)(kbase + bk) * VOCAB + n0 + bn;
        if (full) {
            cp16(bsb[buf], wrow);
            cp16(bsb[buf] + 16, wrow + 8);
        } else {
            #pragma unroll
            for (int j = 0; j < 2; j++) {
                int col = n0 + bn + j * 8;
                int vb = (VOCAB - col) * 2;
                vb = vb < 0 ? 0 : (vb > 16 ? 16 : vb);
                cp16z(bsb[buf] + j * 16, wrow + j * 8, vb);
            }
        }
        CP_COMMIT();
    };

    issue(0, 0);
    for (int c = 0; c < NC; c++) {
        int buf = c & 1;
        if (c + 1 < NC) { issue(c + 1, buf ^ 1); CP_WAIT(1); }
        else            { CP_WAIT(0); }
        __syncthreads();
        #pragma unroll
        for (int kk = 0; kk < 32; kk += 16) {
            uint32_t afr[4][4], bfr[4][2];
            #pragma unroll
            for (int mt = 0; mt < 4; mt++) {
                int m = wm * 64 + mt * 16;
                ldsm4(afr[mt], asw[buf] + ((m + lrow) * 40 + kk + lcol) * 2);
            }
            #pragma unroll
            for (int nh = 0; nh < 2; nh++) {
                uint32_t br[4];
                int nb = wn * 32 + nh * 16;
                ldsm4t(br, bsw[buf] + ((kk + lrow) * 136 + nb + lcol) * 2);
                bfr[nh * 2 + 0][0] = br[0]; bfr[nh * 2 + 0][1] = br[1];
                bfr[nh * 2 + 1][0] = br[2]; bfr[nh * 2 + 1][1] = br[3];
            }
            #pragma unroll
            for (int mt = 0; mt < 4; mt++)
                #pragma unroll
                for (int nt = 0; nt < 4; nt++)
                    mma_f16(acc[mt][nt], afr[mt], bfr[nt]);
        }
        __syncthreads();
    }
    #pragma unroll
    for (int mt = 0; mt < 4; mt++) {
        int row = m0 + wm * 64 + mt * 16 + g;
        #pragma unroll
        for (int rh = 0; rh < 2; rh++) {
            int r = row + rh * 8;
            if (r >= TSTEP * BATCH) continue;
            int tt = r / BATCH, bb = r % BATCH;
            bool act = tt < (lengths[bb] - 1);
            float* orow = out + ((size_t)bb * TSTEP + tt) * VOCAB;
            #pragma unroll
            for (int nt = 0; nt < 4; nt++) {
                int col = n0 + wn * 32 + nt * 8 + 2 * t4;
                if (col < VOCAB)
                    orow[col] = act ? (acc[mt][nt][rh * 2 + 0] + bias[col]) : 0.f;
                if (col + 1 < VOCAB)
                    orow[col + 1] = act ? (acc[mt][nt][rh * 2 + 1] + bias[col + 1]) : 0.f;
            }
        }
    }
}

// ---------------------------------------------------------------------------
// merged scores + softmax + alpha + context + gate. grid(64), 512 threads.
// (validated for correctness in R10; ctx inner loop unrolled 8)
// ---------------------------------------------------------------------------
__global__ void __launch_bounds__(512)
attn_ctx_kernel(const float* __restrict__ dec_att_b,
                const float* __restrict__ full_att_w,
                const float* __restrict__ full_att_b,
                const float* __restrict__ f_beta_b,
                const int* __restrict__ lengths,
                float* __restrict__ out_alpha, int t, int nsplit) {
    __shared__ float att2s[ATTD];
    __shared__ float fws[ATTD];
    __shared__ float sc[PIX];
    __shared__ float als[PIX];
    __shared__ float red[16];
    int b = blockIdx.x, tid = threadIdx.x;
    int warp = tid >> 5, lane = tid & 31;

    {   // att2 sum: tid covers 512 exactly
        float v = dec_att_b[tid];
        for (int s = 0; s < nsplit; s++) v += g_part[(size_t)(s * BATCH + b) * 2560 + tid];
        att2s[tid] = v;
        fws[tid] = full_att_w[tid];
    }
    __syncthreads();

    // scores: 16 warps over p
    float fb = full_att_b[0];
    for (int p = warp; p < PIX; p += 16) {
        const __half2* arow = (const __half2*)(g_att1h + ((size_t)(b * PIX + p)) * ATTD);
        float s = 0.f;
        #pragma unroll
        for (int i = 0; i < 8; i++) {
            int a2 = lane + i * 32;
            float2 v = __half22float2(arow[a2]);
            s += fmaxf(v.x + att2s[2 * a2], 0.f) * fws[2 * a2]
               + fmaxf(v.y + att2s[2 * a2 + 1], 0.f) * fws[2 * a2 + 1];
        }
        #pragma unroll
        for (int o = 16; o; o >>= 1) s += __shfl_xor_sync(~0u, s, o);
        if (!lane) sc[p] = s + fb;
    }
    __syncthreads();

    // softmax
    float v = (tid < PIX) ? sc[tid] : -1e30f;
    float m = v;
    #pragma unroll
    for (int o = 16; o; o >>= 1) m = fmaxf(m, __shfl_xor_sync(~0u, m, o));
    if (!lane) red[warp] = m;
    __syncthreads();
    if (tid == 0) {
        float mm = red[0];
        for (int i = 1; i < 16; i++) mm = fmaxf(mm, red[i]);
        red[0] = mm;
    }
    __syncthreads();
    float mx = red[0];
    float e = (tid < PIX) ? __expf(v - mx) : 0.f;
    float s2 = e;
    #pragma unroll
    for (int o = 16; o; o >>= 1) s2 += __shfl_xor_sync(~0u, s2, o);
    __syncthreads();
    if (!lane) red[warp] = s2;
    __syncthreads();
    if (tid == 0) {
        float ss = 0.f;
        for (int i = 0; i < 16; i++) ss += red[i];
        red[0] = ss;
    }
    __syncthreads();
    float inv = 1.f / red[0];
    if (tid < PIX) {
        float al = e * inv;
        als[tid] = al;
        bool active = t < (lengths[b] - 1);
        out_alpha[((size_t)b * TSTEP + t) * PIX + tid] = active ? al : 0.f;
    }
    __syncthreads();

    // context: thread owns e = 4*tid .. 4*tid+3 (one float2 of halves per p)
    const float2* base = (const float2*)(g_ench + (size_t)b * PIX * ENCD) + tid;
    float c[4];
    #pragma unroll
    for (int j = 0; j < 4; j++) c[j] = 0.f;
    #pragma unroll 8
    for (int p = 0; p < PIX; p++) {
        float2 raw = base[(size_t)p * (ENCD / 4)];
        float al = als[p];
        const __half2* h = (const __half2*)&raw;
        float2 w0 = __half22float2(h[0]);
        float2 w1 = __half22float2(h[1]);
        c[0] += al * w0.x; c[1] += al * w0.y;
        c[2] += al * w1.x; c[3] += al * w1.y;
    }
    int e0 = 4 * tid;
    float4 gp4 = *(const float4*)(f_beta_b + e0);
    float gp[4] = { gp4.x, gp4.y, gp4.z, gp4.w };
    for (int s = 0; s < nsplit; s++) {
        float4 q = *(const float4*)(g_part + (size_t)(s * BATCH + b) * 2560 + 512 + e0);
        gp[0] += q.x; gp[1] += q.y; gp[2] += q.z; gp[3] += q.w;
    }
    __half2 outh[2];
    outh[0] = __floats2half2_rn(c[0] / (1.f + __expf(-gp[0])),
                                c[1] / (1.f + __expf(-gp[1])));
    outh[1] = __floats2half2_rn(c[2] / (1.f + __expf(-gp[2])),
                                c[3] / (1.f + __expf(-gp[3])));
    *((float2*)(g_xh + b * XDIM + EMBD + e0)) = *(const float2*)outh;
}

// ---------------------------------------------------------------------------
__global__ void init_x0_kernel(const float* __restrict__ emb,
                               const int* __restrict__ captions) {
    int b = blockIdx.x, d = threadIdx.x;
    int cap = captions[b * MAXLN];
    g_xh[b * XDIM + d] = __float2half(emb[(size_t)cap * EMBD + d]);
    g_xh[b * XDIM + EMBD + ENCD + d] = __float2half(g_h[b * DECD + d]);
}

__global__ void lstm_kernel(const float* __restrict__ b_ih, const float* __restrict__ b_hh,
                            const int* __restrict__ lengths,
                            const float* __restrict__ emb, const int* __restrict__ captions,
                            int t, int nsplit) {
    int b = blockIdx.x, d = threadIdx.x;
    float g4[4];
    #pragma unroll
    for (int gi = 0; gi < 4; gi++) {
        int n = gi * 512 + d;
        float v = b_ih[n] + b_hh[n];
        for (int s = 0; s < nsplit; s++) v += g_part[(size_t)(s * BATCH + b) * 2048 + n];
        g4[gi] = v;
    }
    float ig = 1.f / (1.f + __expf(-g4[0]));
    float fg = 1.f / (1.f + __expf(-g4[1]));
    float gg = tanhf(g4[2]);
    float og = 1.f / (1.f + __expf(-g4[3]));
    float cold = g_c[b * DECD + d];
    float cn = fg * cold + ig * gg;
    float hn = og * tanhf(cn);
    g_hallh[(size_t)(t * BATCH + b) * DECD + d] = __float2half(hn);
    bool act = t < (lengths[b] - 1);
    float hold = g_h[b * DECD + d];
    float hcur = act ? hn : hold;
    if (act) {
        g_h[b * DECD + d] = hn;
        g_c[b * DECD + d] = cn;
    }
    g_hh[b * DECD + d] = __float2half(hcur);
    if (t + 1 < TSTEP) {
        g_xh[b * XDIM + EMBD + ENCD + d] = __float2half(hcur);
        int cap = captions[b * MAXLN + t + 1];
        g_xh[b * XDIM + d] = __float2half(emb[(size_t)cap * EMBD + d]);
    }
}

// ---------------------------------------------------------------------------
extern "C" void kernel_launch(void* const* d_in, const int* in_sizes, int n_in,
                              void* d_out, int out_size) {
    const float* enc        = (const float*)d_in[0];
    const int*   captions   = (const int*)  d_in[1];
    const int*   lengths    = (const int*)  d_in[2];
    const float* emb        = (const float*)d_in[3];
    const float* enc_att_w  = (const float*)d_in[4];
    const float* enc_att_b  = (const float*)d_in[5];
    const float* dec_att_w  = (const float*)d_in[6];
    const float* dec_att_b  = (const float*)d_in[7];
    const float* full_att_w = (const float*)d_in[8];
    const float* full_att_b = (const float*)d_in[9];
    const float* w_ih       = (const float*)d_in[10];
    const float* b_ih       = (const float*)d_in[11];
    const float* w_hh       = (const float*)d_in[12];
    const float* b_hh       = (const float*)d_in[13];
    const float* init_h_w   = (const float*)d_in[14];
    const float* init_h_b   = (const float*)d_in[15];
    const float* init_c_w   = (const float*)d_in[16];
    const float* init_c_b   = (const float*)d_in[17];
    const float* f_beta_w   = (const float*)d_in[18];
    const float* f_beta_b   = (const float*)d_in[19];
    const float* fc_w       = (const float*)d_in[20];
    const float* fc_b       = (const float*)d_in[21];

    float* out       = (float*)d_out;
    float* out_alpha = out + (size_t)BATCH * TSTEP * VOCAB;

    __half *p_ench, *p_watt, *p_wfb, *p_wih, *p_whh, *p_wenc, *p_wh0, *p_wc0, *p_wfc;
    cudaGetSymbolAddress((void**)&p_ench, g_ench);
    cudaGetSymbolAddress((void**)&p_watt, g_w_att);
    cudaGetSymbolAddress((void**)&p_wfb,  g_w_fb);
    cudaGetSymbolAddress((void**)&p_wih,  g_w_ih);
    cudaGetSymbolAddress((void**)&p_whh,  g_w_hh);
    cudaGetSymbolAddress((void**)&p_wenc, g_w_enc);
    cudaGetSymbolAddress((void**)&p_wh0,  g_w_h0);
    cudaGetSymbolAddress((void**)&p_wc0,  g_w_c0);
    cudaGetSymbolAddress((void**)&p_wfc,  g_w_fc);

    // ---- single batched conversion launch ----
    F2HJobs jobs;
    const float* srcs[NJOBS] = { enc, dec_att_w, f_beta_w, w_ih, w_hh,
                                 enc_att_w, init_h_w, init_c_w, fc_w };
    __half* dsts[NJOBS] = { p_ench, p_watt, p_wfb, p_wih, p_whh,
                            p_wenc, p_wh0, p_wc0, p_wfc };
    int ns[NJOBS] = { BATCH * PIX * ENCD, ATTD * ATTD, DECD * ENCD,
                      (EMBD + ENCD) * 2048, DECD * 2048, ENCD * ATTD,
                      ENCD * DECD, ENCD * DECD, DECD * VOCAB };
    int acc = 0;
    for (int j = 0; j < NJOBS; j++) {
        jobs.src[j] = srcs[j];
        jobs.dst[j] = dsts[j];
        jobs.n8[j] = ns[j] / 8;
        jobs.start[j] = acc;
        acc += (jobs.n8[j] + 255) / 256;
    }
    jobs.start[NJOBS] = acc;
    f2h_all_kernel<<<acc, 256>>>(jobs);

    // ---- setup ----
    mean_kernel<<<dim3(BATCH, ENCD / 256), 256>>>(enc);
    // fused h0|c0: N=1024 = [init_h_w | init_c_w], K=2048 split 16
    gemm64_h<<<dim3(8, 16), 256>>>(XSEL_MEAN, ENCD, p_wh0, DECD, DECD,
                                   p_wc0, DECD, 1 << 30, nullptr, 1024, 128);
    finish_hc_kernel<<<BATCH, 512>>>(init_h_b, init_c_b);
    init_x0_kernel<<<BATCH, 512>>>(emb, captions);
    att1_h<<<dim3((BATCH * PIX) / 128, ATTD / 128), 256>>>(p_ench, p_wenc, enc_att_b);

    // ---- decode: 4 launches per step ----
    for (int t = 0; t < TSTEP; t++) {
        gemm64_h<<<dim3(20, 4), 256>>>(XSEL_H, DECD, p_watt, ATTD, ATTD,
                                       p_wfb, ENCD, DECD, nullptr, 2560, 128);
        attn_ctx_kernel<<<BATCH, 512>>>(dec_att_b, full_att_w, full_att_b, f_beta_b,
                                        lengths, out_alpha, t, 4);
        gemm64_h<<<dim3(16, 8), 256>>>(XSEL_X, XDIM, p_wih, 2048, 2048,
                                       nullptr, 0, EMBD + ENCD, p_whh, 2048, 384);
        lstm_kernel<<<BATCH, 512>>>(b_ih, b_hh, lengths, emb, captions, t, 8);
    }

    // ---- deferred fc ----
    fc_h<<<dim3((VOCAB + 127) / 128, MROWS / 128), 256>>>(p_wfc, fc_b, lengths, out);
}

// round 15
// speedup vs baseline: 1.2347x; 1.0185x over previous
#include <cuda_runtime.h>
#include <cuda_fp16.h>
#include <cstdint>
#include <cstddef>

#define BATCH 64
#define PIX   196
#define ENCD  2048
#define ATTD  512
#define EMBD  512
#define DECD  512
#define VOCAB 20000
#define MAXLN 22
#define TSTEP 21
#define XDIM  3072
#define MROWS 1408   // 11*128 >= 21*64=1344

// ---------------- fp32 scratch ----------------
__device__ float g_h[BATCH * DECD];
__device__ float g_c[BATCH * DECD];
__device__ __align__(16) float g_part[16 * BATCH * 2560];

// ---------------- fp16 activations ----------------
__device__ __align__(16) __half g_att1h[BATCH * PIX * ATTD];
__device__ __align__(16) __half g_ench[BATCH * PIX * ENCD];
__device__ __align__(16) __half g_meanh[BATCH * ENCD];
__device__ __align__(16) __half g_hh[BATCH * DECD];
__device__ __align__(16) __half g_xh[BATCH * XDIM];
__device__ __align__(16) __half g_hallh[MROWS * DECD];

// ---------------- fp16 weights ----------------
__device__ __align__(16) __half g_w_att[ATTD * ATTD];
__device__ __align__(16) __half g_w_fb[DECD * ENCD];
__device__ __align__(16) __half g_w_ih[(EMBD + ENCD) * 2048];
__device__ __align__(16) __half g_w_hh[DECD * 2048];
__device__ __align__(16) __half g_w_enc[ENCD * ATTD];
__device__ __align__(16) __half g_w_h0[ENCD * DECD];
__device__ __align__(16) __half g_w_c0[ENCD * DECD];
__device__ __align__(16) __half g_w_fc[DECD * VOCAB];

// ---------------------------------------------------------------------------
__device__ __forceinline__ void mma_f16(float* d, const uint32_t* a, const uint32_t* b) {
    asm volatile(
        "mma.sync.aligned.m16n8k16.row.col.f32.f16.f16.f32 "
        "{%0,%1,%2,%3}, {%4,%5,%6,%7}, {%8,%9}, {%0,%1,%2,%3};\n"
        : "+f"(d[0]), "+f"(d[1]), "+f"(d[2]), "+f"(d[3])
        : "r"(a[0]), "r"(a[1]), "r"(a[2]), "r"(a[3]), "r"(b[0]), "r"(b[1]));
}
__device__ __forceinline__ void ldsm4(uint32_t* r, uint32_t addr) {
    asm volatile("ldmatrix.sync.aligned.m8n8.x4.shared.b16 {%0,%1,%2,%3}, [%4];"
                 : "=r"(r[0]), "=r"(r[1]), "=r"(r[2]), "=r"(r[3]) : "r"(addr));
}
__device__ __forceinline__ void ldsm4t(uint32_t* r, uint32_t addr) {
    asm volatile("ldmatrix.sync.aligned.m8n8.x4.trans.shared.b16 {%0,%1,%2,%3}, [%4];"
                 : "=r"(r[0]), "=r"(r[1]), "=r"(r[2]), "=r"(r[3]) : "r"(addr));
}
__device__ __forceinline__ void cp16(uint32_t dst, const void* src) {
    asm volatile("cp.async.cg.shared.global [%0], [%1], 16;\n" :: "r"(dst), "l"(src));
}
__device__ __forceinline__ void cp16z(uint32_t dst, const void* src, int srcbytes) {
    asm volatile("cp.async.cg.shared.global [%0], [%1], 16, %2;\n"
                 :: "r"(dst), "l"(src), "r"(srcbytes));
}
#define CP_COMMIT() asm volatile("cp.async.commit_group;\n")
#define CP_WAIT(n)  asm volatile("cp.async.wait_group %0;\n" :: "n"(n))

// ---------------------------------------------------------------------------
// batched fp32->fp16 conversion (one launch for all tensors)
// ---------------------------------------------------------------------------
#define NJOBS 9
struct F2HJobs {
    const float* src[NJOBS];
    __half* dst[NJOBS];
    int n8[NJOBS];
    int start[NJOBS + 1];
};

__global__ void f2h_all_kernel(F2HJobs jobs) {
    int bx = blockIdx.x;
    int j = 0;
    #pragma unroll
    for (int q = 0; q < NJOBS; q++)
        if (bx >= jobs.start[q + 1]) j = q + 1;
    int i = (bx - jobs.start[j]) * 256 + threadIdx.x;
    if (i >= jobs.n8[j]) return;
    const float4* s = (const float4*)jobs.src[j];
    float4 a = s[2 * i], b = s[2 * i + 1];
    __half2* d = (__half2*)jobs.dst[j];
    d[4 * i + 0] = __floats2half2_rn(a.x, a.y);
    d[4 * i + 1] = __floats2half2_rn(a.z, a.w);
    d[4 * i + 2] = __floats2half2_rn(b.x, b.y);
    d[4 * i + 3] = __floats2half2_rn(b.z, b.w);
}

__global__ void mean_kernel(const float* __restrict__ enc) {
    int b = blockIdx.x;
    int e = blockIdx.y * 256 + threadIdx.x;
    const float* base = enc + (size_t)b * PIX * ENCD + e;
    float s = 0.f;
    #pragma unroll 4
    for (int p = 0; p < PIX; p++) s += base[(size_t)p * ENCD];
    g_meanh[b * ENCD + e] = __float2half(s * (1.0f / PIX));
}

// ---------------------------------------------------------------------------
#define XSEL_H    0
#define XSEL_MEAN 1
#define XSEL_X    2

// M=64 fp16 GEMM via ldmatrix, split-K, N/K-concat. Tile 64x128, 2-stage.
__global__ void gemm64_h(int xsel, int ldx,
                         const __half* __restrict__ Wa, int lda, int na,
                         const __half* __restrict__ Wb, int ldb,
                         int rows1, const __half* __restrict__ W2k,
                         int N, int KS)
{
    __shared__ __align__(16) __half As[2][64 * 40];
    __shared__ __align__(16) __half Bs[2][32 * 136];
    const __half* X = (xsel == XSEL_H) ? g_hh : (xsel == XSEL_MEAN) ? g_meanh : g_xh;
    int n0 = blockIdx.x * 128;
    int s  = blockIdx.y;
    int tid = threadIdx.x;
    int lane = tid & 31, warp = tid >> 5;
    int wm = warp >> 2, wn = warp & 3;
    int g = lane >> 2, t4 = lane & 3;

    const __half* Wsel; int ld, coloff;
    if (n0 < na) { Wsel = Wa; ld = lda; coloff = n0; }
    else         { Wsel = Wb; ld = ldb; coloff = n0 - na; }

    float acc[2][4][4];
    #pragma unroll
    for (int i = 0; i < 2; i++)
        #pragma unroll
        for (int j = 0; j < 4; j++)
            #pragma unroll
            for (int q = 0; q < 4; q++) acc[i][j][q] = 0.f;

    int ar = tid >> 2, ak = (tid & 3) * 8;
    int bk = tid >> 3, bn = (tid & 7) * 16;
    int lrow = (lane & 7) + ((lane & 8) ? 8 : 0);
    int lcol = (lane & 16) ? 8 : 0;
    uint32_t asw[2], bsw[2], asb[2], bsb[2];
    #pragma unroll
    for (int u = 0; u < 2; u++) {
        asw[u] = (uint32_t)__cvta_generic_to_shared(&As[u][0]);
        bsw[u] = (uint32_t)__cvta_generic_to_shared(&Bs[u][0]);
        asb[u] = asw[u] + (ar * 40 + ak) * 2;
        bsb[u] = bsw[u] + (bk * 136 + bn) * 2;
    }
    int NC = KS / 32;

    auto issue = [&](int c, int buf) {
        int kbase = s * KS + c * 32;
        cp16(asb[buf], X + (size_t)ar * ldx + kbase + ak);
        int kg = kbase + bk;
        const __half* wrow = (kg < rows1)
            ? (Wsel + (size_t)kg * ld + coloff)
            : (W2k + (size_t)(kg - rows1) * ld + coloff);
        cp16(bsb[buf], wrow + bn);
        cp16(bsb[buf] + 16, wrow + bn + 8);
        CP_COMMIT();
    };

    issue(0, 0);
    for (int c = 0; c < NC; c++) {
        int buf = c & 1;
        if (c + 1 < NC) { issue(c + 1, buf ^ 1); CP_WAIT(1); }
        else            { CP_WAIT(0); }
        __syncthreads();
        #pragma unroll
        for (int kk = 0; kk < 32; kk += 16) {
            uint32_t afr[2][4], bfr[4][2];
            #pragma unroll
            for (int mt = 0; mt < 2; mt++) {
                int m = wm * 32 + mt * 16;
                ldsm4(afr[mt], asw[buf] + ((m + lrow) * 40 + kk + lcol) * 2);
            }
            #pragma unroll
            for (int nh = 0; nh < 2; nh++) {
                uint32_t br[4];
                int nb = wn * 32 + nh * 16;
                ldsm4t(br, bsw[buf] + ((kk + lrow) * 136 + nb + lcol) * 2);
                bfr[nh * 2 + 0][0] = br[0]; bfr[nh * 2 + 0][1] = br[1];
                bfr[nh * 2 + 1][0] = br[2]; bfr[nh * 2 + 1][1] = br[3];
            }
            #pragma unroll
            for (int mt = 0; mt < 2; mt++)
                #pragma unroll
                for (int nt = 0; nt < 4; nt++)
                    mma_f16(acc[mt][nt], afr[mt], bfr[nt]);
        }
        __syncthreads();
    }
    #pragma unroll
    for (int mt = 0; mt < 2; mt++) {
        int row = wm * 32 + mt * 16 + g;
        #pragma unroll
        for (int nt = 0; nt < 4; nt++) {
            int col = n0 + wn * 32 + nt * 8 + 2 * t4;
            float* p0 = g_part + (size_t)(s * BATCH + row) * N + col;
            p0[0] = acc[mt][nt][0]; p0[1] = acc[mt][nt][1];
            float* p1 = p0 + (size_t)8 * N;
            p1[0] = acc[mt][nt][2]; p1[1] = acc[mt][nt][3];
        }
    }
}

// finish h0/c0 from fused N=1024 GEMM partials
__global__ void finish_hc_kernel(const float* __restrict__ hb, const float* __restrict__ cb) {
    int b = blockIdx.x, d = threadIdx.x;   // 512 threads
    float vh = hb[d], vc = cb[d];
    for (int s = 0; s < 16; s++) {
        const float* pp = g_part + (size_t)(s * BATCH + b) * 1024;
        vh += pp[d];
        vc += pp[512 + d];
    }
    g_h[b * DECD + d] = vh;
    g_c[b * DECD + d] = vc;
    g_hh[b * DECD + d] = __float2half(vh);
}

// ---------------------------------------------------------------------------
// att1 (one-time): 12544x512 fp16 GEMM + bias -> fp16 g_att1h. Tile 128x128.
// ---------------------------------------------------------------------------
__global__ void att1_h(const __half* __restrict__ A, const __half* __restrict__ W,
                       const float* __restrict__ bias) {
    __shared__ __align__(16) __half As[2][128 * 40];
    __shared__ __align__(16) __half Bs[2][32 * 136];
    int m0 = blockIdx.x * 128, n0 = blockIdx.y * 128;
    int tid = threadIdx.x;
    int lane = tid & 31, warp = tid >> 5;
    int wm = warp >> 2, wn = warp & 3;
    int g = lane >> 2, t4 = lane & 3;

    float acc[4][4][4];
    #pragma unroll
    for (int i = 0; i < 4; i++)
        #pragma unroll
        for (int j = 0; j < 4; j++)
            #pragma unroll
            for (int q = 0; q < 4; q++) acc[i][j][q] = 0.f;

    int ar = tid >> 1, ak = (tid & 1) * 16;
    int bk = tid >> 3, bn = (tid & 7) * 16;
    int lrow = (lane & 7) + ((lane & 8) ? 8 : 0);
    int lcol = (lane & 16) ? 8 : 0;
    uint32_t asw[2], bsw[2], asb[2], bsb[2];
    #pragma unroll
    for (int u = 0; u < 2; u++) {
        asw[u] = (uint32_t)__cvta_generic_to_shared(&As[u][0]);
        bsw[u] = (uint32_t)__cvta_generic_to_shared(&Bs[u][0]);
        asb[u] = asw[u] + (ar * 40 + ak) * 2;
        bsb[u] = bsw[u] + (bk * 136 + bn) * 2;
    }
    const int NC = ENCD / 32;

    auto issue = [&](int c, int buf) {
        int kbase = c * 32;
        const __half* ap = A + (size_t)(m0 + ar) * ENCD + kbase + ak;
        cp16(asb[buf], ap);
        cp16(asb[buf] + 16, ap + 8);
        const __half* wrow = W + (size_t)(kbase + bk) * ATTD + n0 + bn;
        cp16(bsb[buf], wrow);
        cp16(bsb[buf] + 16, wrow + 8);
        CP_COMMIT();
    };

    issue(0, 0);
    for (int c = 0; c < NC; c++) {
        int buf = c & 1;
        if (c + 1 < NC) { issue(c + 1, buf ^ 1); CP_WAIT(1); }
        else            { CP_WAIT(0); }
        __syncthreads();
        #pragma unroll
        for (int kk = 0; kk < 32; kk += 16) {
            uint32_t afr[4][4], bfr[4][2];
            #pragma unroll
            for (int mt = 0; mt < 4; mt++) {
                int m = wm * 64 + mt * 16;
                ldsm4(afr[mt], asw[buf] + ((m + lrow) * 40 + kk + lcol) * 2);
            }
            #pragma unroll
            for (int nh = 0; nh < 2; nh++) {
                uint32_t br[4];
                int nb = wn * 32 + nh * 16;
                ldsm4t(br, bsw[buf] + ((kk + lrow) * 136 + nb + lcol) * 2);
                bfr[nh * 2 + 0][0] = br[0]; bfr[nh * 2 + 0][1] = br[1];
                bfr[nh * 2 + 1][0] = br[2]; bfr[nh * 2 + 1][1] = br[3];
            }
            #pragma unroll
            for (int mt = 0; mt < 4; mt++)
                #pragma unroll
                for (int nt = 0; nt < 4; nt++)
                    mma_f16(acc[mt][nt], afr[mt], bfr[nt]);
        }
        __syncthreads();
    }
    #pragma unroll
    for (int mt = 0; mt < 4; mt++) {
        int row = m0 + wm * 64 + mt * 16 + g;
        #pragma unroll
        for (int nt = 0; nt < 4; nt++) {
            int col = n0 + wn * 32 + nt * 8 + 2 * t4;
            float b0 = bias[col], b1 = bias[col + 1];
            __half2* p0 = (__half2*)(g_att1h + (size_t)row * ATTD) + (col >> 1);
            *p0 = __floats2half2_rn(acc[mt][nt][0] + b0, acc[mt][nt][1] + b1);
            __half2* p1 = (__half2*)(g_att1h + (size_t)(row + 8) * ATTD) + (col >> 1);
            *p1 = __floats2half2_rn(acc[mt][nt][2] + b0, acc[mt][nt][3] + b1);
        }
    }
}

// ---------------------------------------------------------------------------
// fc (deferred): 1344x20000 fp16 GEMM, masked epilogue. Tile 128x128.
// ---------------------------------------------------------------------------
__global__ void fc_h(const __half* __restrict__ W, const float* __restrict__ bias,
                     const int* __restrict__ lengths, float* __restrict__ out) {
    __shared__ __align__(16) __half As[2][128 * 40];
    __shared__ __align__(16) __half Bs[2][32 * 136];
    int n0 = blockIdx.x * 128, m0 = blockIdx.y * 128;
    int tid = threadIdx.x;
    int lane = tid & 31, warp = tid >> 5;
    int wm = warp >> 2, wn = warp & 3;
    int g = lane >> 2, t4 = lane & 3;
    bool full = (n0 + 128 <= VOCAB);

    float acc[4][4][4];
    #pragma unroll
    for (int i = 0; i < 4; i++)
        #pragma unroll
        for (int j = 0; j < 4; j++)
            #pragma unroll
            for (int q = 0; q < 4; q++) acc[i][j][q] = 0.f;

    int ar = tid >> 1, ak = (tid & 1) * 16;
    int bk = tid >> 3, bn = (tid & 7) * 16;
    int lrow = (lane & 7) + ((lane & 8) ? 8 : 0);
    int lcol = (lane & 16) ? 8 : 0;
    uint32_t asw[2], bsw[2], asb[2], bsb[2];
    #pragma unroll
    for (int u = 0; u < 2; u++) {
        asw[u] = (uint32_t)__cvta_generic_to_shared(&As[u][0]);
        bsw[u] = (uint32_t)__cvta_generic_to_shared(&Bs[u][0]);
        asb[u] = asw[u] + (ar * 40 + ak) * 2;
        bsb[u] = bsw[u] + (bk * 136 + bn) * 2;
    }
    const int NC = DECD / 32;

    auto issue = [&](int c, int buf) {
        int kbase = c * 32;
        const __half* ap = g_hallh + (size_t)(m0 + ar) * DECD + kbase + ak;
        cp16(asb[buf], ap);
        cp16(asb[buf] + 16, ap + 8);
        const __half* wrow = W + (size_t)(kbase + bk) * VOCAB + n0 + bn;
        if (full) {
            cp16(bsb[buf], wrow);
            cp16(bsb[buf] + 16, wrow + 8);
        } else {
            #pragma unroll
            for (int j = 0; j < 2; j++) {
                int col = n0 + bn + j * 8;
                int vb = (VOCAB - col) * 2;
                vb = vb < 0 ? 0 : (vb > 16 ? 16 : vb);
                cp16z(bsb[buf] + j * 16, wrow + j * 8, vb);
            }
        }
        CP_COMMIT();
    };

    issue(0, 0);
    for (int c = 0; c < NC; c++) {
        int buf = c & 1;
        if (c + 1 < NC) { issue(c + 1, buf ^ 1); CP_WAIT(1); }
        else            { CP_WAIT(0); }
        __syncthreads();
        #pragma unroll
        for (int kk = 0; kk < 32; kk += 16) {
            uint32_t afr[4][4], bfr[4][2];
            #pragma unroll
            for (int mt = 0; mt < 4; mt++) {
                int m = wm * 64 + mt * 16;
                ldsm4(afr[mt], asw[buf] + ((m + lrow) * 40 + kk + lcol) * 2);
            }
            #pragma unroll
            for (int nh = 0; nh < 2; nh++) {
                uint32_t br[4];
                int nb = wn * 32 + nh * 16;
                ldsm4t(br, bsw[buf] + ((kk + lrow) * 136 + nb + lcol) * 2);
                bfr[nh * 2 + 0][0] = br[0]; bfr[nh * 2 + 0][1] = br[1];
                bfr[nh * 2 + 1][0] = br[2]; bfr[nh * 2 + 1][1] = br[3];
            }
            #pragma unroll
            for (int mt = 0; mt < 4; mt++)
                #pragma unroll
                for (int nt = 0; nt < 4; nt++)
                    mma_f16(acc[mt][nt], afr[mt], bfr[nt]);
        }
        __syncthreads();
    }
    #pragma unroll
    for (int mt = 0; mt < 4; mt++) {
        int row = m0 + wm * 64 + mt * 16 + g;
        #pragma unroll
        for (int rh = 0; rh < 2; rh++) {
            int r = row + rh * 8;
            if (r >= TSTEP * BATCH) continue;
            int tt = r / BATCH, bb = r % BATCH;
            bool act = tt < (lengths[bb] - 1);
            float* orow = out + ((size_t)bb * TSTEP + tt) * VOCAB;
            #pragma unroll
            for (int nt = 0; nt < 4; nt++) {
                int col = n0 + wn * 32 + nt * 8 + 2 * t4;
                if (col < VOCAB)
                    orow[col] = act ? (acc[mt][nt][rh * 2 + 0] + bias[col]) : 0.f;
                if (col + 1 < VOCAB)
                    orow[col + 1] = act ? (acc[mt][nt][rh * 2 + 1] + bias[col + 1]) : 0.f;
            }
        }
    }
}

// ---------------------------------------------------------------------------
// merged scores + softmax + alpha + context + gate. grid(64), 512 threads.
// Inactive batches: write zero alphas and exit (downstream values masked).
// ---------------------------------------------------------------------------
__global__ void __launch_bounds__(512)
attn_ctx_kernel(const float* __restrict__ dec_att_b,
                const float* __restrict__ full_att_w,
                const float* __restrict__ full_att_b,
                const float* __restrict__ f_beta_b,
                const int* __restrict__ lengths,
                float* __restrict__ out_alpha, int t, int nsplit) {
    __shared__ float att2s[ATTD];
    __shared__ float fws[ATTD];
    __shared__ float sc[PIX];
    __shared__ float als[PIX];
    __shared__ float red[16];
    int b = blockIdx.x, tid = threadIdx.x;
    int warp = tid >> 5, lane = tid & 31;

    bool active = t < (lengths[b] - 1);
    if (!active) {
        if (tid < PIX)
            out_alpha[((size_t)b * TSTEP + t) * PIX + tid] = 0.f;
        return;
    }

    {   // att2 sum: tid covers 512 exactly
        float v = dec_att_b[tid];
        for (int s = 0; s < nsplit; s++) v += g_part[(size_t)(s * BATCH + b) * 2560 + tid];
        att2s[tid] = v;
        fws[tid] = full_att_w[tid];
    }
    __syncthreads();

    // scores: 16 warps over p
    float fb = full_att_b[0];
    for (int p = warp; p < PIX; p += 16) {
        const __half2* arow = (const __half2*)(g_att1h + ((size_t)(b * PIX + p)) * ATTD);
        float s = 0.f;
        #pragma unroll
        for (int i = 0; i < 8; i++) {
            int a2 = lane + i * 32;
            float2 v = __half22float2(arow[a2]);
            s += fmaxf(v.x + att2s[2 * a2], 0.f) * fws[2 * a2]
               + fmaxf(v.y + att2s[2 * a2 + 1], 0.f) * fws[2 * a2 + 1];
        }
        #pragma unroll
        for (int o = 16; o; o >>= 1) s += __shfl_xor_sync(~0u, s, o);
        if (!lane) sc[p] = s + fb;
    }
    __syncthreads();

    // softmax
    float v = (tid < PIX) ? sc[tid] : -1e30f;
    float m = v;
    #pragma unroll
    for (int o = 16; o; o >>= 1) m = fmaxf(m, __shfl_xor_sync(~0u, m, o));
    if (!lane) red[warp] = m;
    __syncthreads();
    if (tid == 0) {
        float mm = red[0];
        for (int i = 1; i < 16; i++) mm = fmaxf(mm, red[i]);
        red[0] = mm;
    }
    __syncthreads();
    float mx = red[0];
    float e = (tid < PIX) ? __expf(v - mx) : 0.f;
    float s2 = e;
    #pragma unroll
    for (int o = 16; o; o >>= 1) s2 += __shfl_xor_sync(~0u, s2, o);
    __syncthreads();
    if (!lane) red[warp] = s2;
    __syncthreads();
    if (tid == 0) {
        float ss = 0.f;
        for (int i = 0; i < 16; i++) ss += red[i];
        red[0] = ss;
    }
    __syncthreads();
    float inv = 1.f / red[0];
    if (tid < PIX) {
        float al = e * inv;
        als[tid] = al;
        out_alpha[((size_t)b * TSTEP + t) * PIX + tid] = al;
    }
    __syncthreads();

    // context: thread owns e = 4*tid .. 4*tid+3 (one float2 of halves per p)
    const float2* base = (const float2*)(g_ench + (size_t)b * PIX * ENCD) + tid;
    float c[4];
    #pragma unroll
    for (int j = 0; j < 4; j++) c[j] = 0.f;
    #pragma unroll 8
    for (int p = 0; p < PIX; p++) {
        float2 raw = base[(size_t)p * (ENCD / 4)];
        float al = als[p];
        const __half2* h = (const __half2*)&raw;
        float2 w0 = __half22float2(h[0]);
        float2 w1 = __half22float2(h[1]);
        c[0] += al * w0.x; c[1] += al * w0.y;
        c[2] += al * w1.x; c[3] += al * w1.y;
    }
    int e0 = 4 * tid;
    float4 gp4 = *(const float4*)(f_beta_b + e0);
    float gp[4] = { gp4.x, gp4.y, gp4.z, gp4.w };
    for (int s = 0; s < nsplit; s++) {
        float4 q = *(const float4*)(g_part + (size_t)(s * BATCH + b) * 2560 + 512 + e0);
        gp[0] += q.x; gp[1] += q.y; gp[2] += q.z; gp[3] += q.w;
    }
    __half2 outh[2];
    outh[0] = __floats2half2_rn(c[0] / (1.f + __expf(-gp[0])),
                                c[1] / (1.f + __expf(-gp[1])));
    outh[1] = __floats2half2_rn(c[2] / (1.f + __expf(-gp[2])),
                                c[3] / (1.f + __expf(-gp[3])));
    *((float2*)(g_xh + b * XDIM + EMBD + e0)) = *(const float2*)outh;
}

// ---------------------------------------------------------------------------
__global__ void init_x0_kernel(const float* __restrict__ emb,
                               const int* __restrict__ captions) {
    int b = blockIdx.x, d = threadIdx.x;
    int cap = captions[b * MAXLN];
    g_xh[b * XDIM + d] = __float2half(emb[(size_t)cap * EMBD + d]);
    g_xh[b * XDIM + EMBD + ENCD + d] = __float2half(g_h[b * DECD + d]);
}

__global__ void lstm_kernel(const float* __restrict__ b_ih, const float* __restrict__ b_hh,
                            const int* __restrict__ lengths,
                            const float* __restrict__ emb, const int* __restrict__ captions,
                            int t, int nsplit) {
    int b = blockIdx.x, d = threadIdx.x;
    // inactive: h/c keep old values; hallh/x values are masked downstream -> skip all
    if (t >= lengths[b] - 1) return;
    float g4[4];
    #pragma unroll
    for (int gi = 0; gi < 4; gi++) {
        int n = gi * 512 + d;
        float v = b_ih[n] + b_hh[n];
        for (int s = 0; s < nsplit; s++) v += g_part[(size_t)(s * BATCH + b) * 2048 + n];
        g4[gi] = v;
    }
    float ig = 1.f / (1.f + __expf(-g4[0]));
    float fg = 1.f / (1.f + __expf(-g4[1]));
    float gg = tanhf(g4[2]);
    float og = 1.f / (1.f + __expf(-g4[3]));
    float cold = g_c[b * DECD + d];
    float cn = fg * cold + ig * gg;
    float hn = og * tanhf(cn);
    g_hallh[(size_t)(t * BATCH + b) * DECD + d] = __float2half(hn);
    g_h[b * DECD + d] = hn;
    g_c[b * DECD + d] = cn;
    g_hh[b * DECD + d] = __float2half(hn);
    if (t + 1 < TSTEP) {
        g_xh[b * XDIM + EMBD + ENCD + d] = __float2half(hn);
        int cap = captions[b * MAXLN + t + 1];
        g_xh[b * XDIM + d] = __float2half(emb[(size_t)cap * EMBD + d]);
    }
}

// ---------------------------------------------------------------------------
extern "C" void kernel_launch(void* const* d_in, const int* in_sizes, int n_in,
                              void* d_out, int out_size) {
    const float* enc        = (const float*)d_in[0];
    const int*   captions   = (const int*)  d_in[1];
    const int*   lengths    = (const int*)  d_in[2];
    const float* emb        = (const float*)d_in[3];
    const float* enc_att_w  = (const float*)d_in[4];
    const float* enc_att_b  = (const float*)d_in[5];
    const float* dec_att_w  = (const float*)d_in[6];
    const float* dec_att_b  = (const float*)d_in[7];
    const float* full_att_w = (const float*)d_in[8];
    const float* full_att_b = (const float*)d_in[9];
    const float* w_ih       = (const float*)d_in[10];
    const float* b_ih       = (const float*)d_in[11];
    const float* w_hh       = (const float*)d_in[12];
    const float* b_hh       = (const float*)d_in[13];
    const float* init_h_w   = (const float*)d_in[14];
    const float* init_h_b   = (const float*)d_in[15];
    const float* init_c_w   = (const float*)d_in[16];
    const float* init_c_b   = (const float*)d_in[17];
    const float* f_beta_w   = (const float*)d_in[18];
    const float* f_beta_b   = (const float*)d_in[19];
    const float* fc_w       = (const float*)d_in[20];
    const float* fc_b       = (const float*)d_in[21];

    float* out       = (float*)d_out;
    float* out_alpha = out + (size_t)BATCH * TSTEP * VOCAB;

    __half *p_ench, *p_watt, *p_wfb, *p_wih, *p_whh, *p_wenc, *p_wh0, *p_wc0, *p_wfc;
    cudaGetSymbolAddress((void**)&p_ench, g_ench);
    cudaGetSymbolAddress((void**)&p_watt, g_w_att);
    cudaGetSymbolAddress((void**)&p_wfb,  g_w_fb);
    cudaGetSymbolAddress((void**)&p_wih,  g_w_ih);
    cudaGetSymbolAddress((void**)&p_whh,  g_w_hh);
    cudaGetSymbolAddress((void**)&p_wenc, g_w_enc);
    cudaGetSymbolAddress((void**)&p_wh0,  g_w_h0);
    cudaGetSymbolAddress((void**)&p_wc0,  g_w_c0);
    cudaGetSymbolAddress((void**)&p_wfc,  g_w_fc);

    // ---- single batched conversion launch ----
    F2HJobs jobs;
    const float* srcs[NJOBS] = { enc, dec_att_w, f_beta_w, w_ih, w_hh,
                                 enc_att_w, init_h_w, init_c_w, fc_w };
    __half* dsts[NJOBS] = { p_ench, p_watt, p_wfb, p_wih, p_whh,
                            p_wenc, p_wh0, p_wc0, p_wfc };
    int ns[NJOBS] = { BATCH * PIX * ENCD, ATTD * ATTD, DECD * ENCD,
                      (EMBD + ENCD) * 2048, DECD * 2048, ENCD * ATTD,
                      ENCD * DECD, ENCD * DECD, DECD * VOCAB };
    int acc = 0;
    for (int j = 0; j < NJOBS; j++) {
        jobs.src[j] = srcs[j];
        jobs.dst[j] = dsts[j];
        jobs.n8[j] = ns[j] / 8;
        jobs.start[j] = acc;
        acc += (jobs.n8[j] + 255) / 256;
    }
    jobs.start[NJOBS] = acc;
    f2h_all_kernel<<<acc, 256>>>(jobs);

    // ---- setup ----
    mean_kernel<<<dim3(BATCH, ENCD / 256), 256>>>(enc);
    // fused h0|c0: N=1024 = [init_h_w | init_c_w], K=2048 split 16
    gemm64_h<<<dim3(8, 16), 256>>>(XSEL_MEAN, ENCD, p_wh0, DECD, DECD,
                                   p_wc0, DECD, 1 << 30, nullptr, 1024, 128);
    finish_hc_kernel<<<BATCH, 512>>>(init_h_b, init_c_b);
    init_x0_kernel<<<BATCH, 512>>>(emb, captions);
    att1_h<<<dim3((BATCH * PIX) / 128, ATTD / 128), 256>>>(p_ench, p_wenc, enc_att_b);

    // ---- decode: 4 launches per step ----
    for (int t = 0; t < TSTEP; t++) {
        gemm64_h<<<dim3(20, 4), 256>>>(XSEL_H, DECD, p_watt, ATTD, ATTD,
                                       p_wfb, ENCD, DECD, nullptr, 2560, 128);
        attn_ctx_kernel<<<BATCH, 512>>>(dec_att_b, full_att_w, full_att_b, f_beta_b,
                                        lengths, out_alpha, t, 4);
        gemm64_h<<<dim3(16, 8), 256>>>(XSEL_X, XDIM, p_wih, 2048, 2048,
                                       nullptr, 0, EMBD + ENCD, p_whh, 2048, 384);
        lstm_kernel<<<BATCH, 512>>>(b_ih, b_hh, lengths, emb, captions, t, 8);
    }

    // ---- deferred fc ----
    fc_h<<<dim3((VOCAB + 127) / 128, MROWS / 128), 256>>>(p_wfc, fc_b, lengths, out);
}